// round 3
// baseline (speedup 1.0000x reference)
#include <cuda_runtime.h>
#include <cuda_bf16.h>
#include <cstddef>

// ---------------- problem constants ----------------
constexpr int Bc = 16;
constexpr int Nc = 128;
constexpr int Mc = 1024;
constexpr int DNc = 512;
constexpr int DEc = 256;
constexpr int WNc = 128;
constexpr int WEc = 128;
constexpr int Pc = 512;
constexpr int HIDc = 256;
constexpr int CI = 512;     // 2*(WN+WE)

// ---------------- scratch (device global, no allocs) ----------------
constexpr size_t OFF_XM    = 0;                       // B*N*DN   = 1048576
constexpr size_t OFF_XWN   = OFF_XM    + (size_t)Bc*Nc*DNc;   // 262144
constexpr size_t OFF_XP    = OFF_XWN   + (size_t)Bc*Nc*WNc;
constexpr size_t OFF_H     = OFF_XP    + (size_t)Bc*Nc*WNc;
constexpr size_t OFF_EG    = OFF_H     + (size_t)Bc*Nc*WNc;   // B*M*DE = 4194304
constexpr size_t OFF_EGWE  = OFF_EG    + (size_t)Bc*Mc*DEc;   // 2097152
constexpr size_t OFF_G     = OFF_EGWE  + (size_t)Bc*Mc*WEc;   // 2097152
constexpr size_t OFF_AGG   = OFF_G     + (size_t)Bc*Mc*WEc;   // 262144
constexpr size_t OFF_PAIRE = OFF_AGG   + (size_t)Bc*Nc*WEc;   // 2097152
constexpr size_t OFF_EQ    = OFF_PAIRE + (size_t)Bc*Pc*DEc;   // 1048576
constexpr size_t OFF_CI    = OFF_EQ    + (size_t)Bc*Pc*WEc;   // 4194304
constexpr size_t OFF_HID   = OFF_CI    + (size_t)Bc*Pc*CI;    // 2097152
constexpr size_t SCRATCH_TOTAL = OFF_HID + (size_t)Bc*Pc*HIDc;

__device__ float d_scratch[SCRATCH_TOTAL];

// ---------------- generic tiled SGEMM: C[M,N] = epi(A[M,K] @ W[K,N]) ----------------
// EPI: 0 none, 1 relu, 3 bias+relu
// Requires: Mr % 64 == 0, Ncols % 64 == 0, K % 16 == 0 (all call sites satisfy this).
template<int EPI>
__global__ void __launch_bounds__(256) gemm_k(
    const float* __restrict__ A, const float* __restrict__ W,
    float* __restrict__ C, int Mr, int K, int Ncols,
    const float* __restrict__ bias)
{
    __shared__ float As[16][68];
    __shared__ float Ws[16][68];
    const int tid = threadIdx.x;
    const int tx = tid & 15, ty = tid >> 4;
    const int rowBase = blockIdx.y * 64;
    const int colBase = blockIdx.x * 64;

    const int a_r  = tid >> 2;            // 0..63
    const int a_k4 = (tid & 3) * 4;       // 0,4,8,12
    const int w_k  = tid >> 4;            // 0..15
    const int w_c4 = (tid & 15) * 4;      // 0..60

    float acc[4][4] = {};

    for (int k0 = 0; k0 < K; k0 += 16) {
        float4 av = *(const float4*)(A + (size_t)(rowBase + a_r) * K + k0 + a_k4);
        As[a_k4 + 0][a_r] = av.x;
        As[a_k4 + 1][a_r] = av.y;
        As[a_k4 + 2][a_r] = av.z;
        As[a_k4 + 3][a_r] = av.w;
        float4 wv = *(const float4*)(W + (size_t)(k0 + w_k) * Ncols + colBase + w_c4);
        *(float4*)&Ws[w_k][w_c4] = wv;
        __syncthreads();
        #pragma unroll
        for (int kk = 0; kk < 16; kk++) {
            float4 ar = *(const float4*)&As[kk][ty * 4];
            float4 wr = *(const float4*)&Ws[kk][tx * 4];
            float a4[4] = {ar.x, ar.y, ar.z, ar.w};
            float w4[4] = {wr.x, wr.y, wr.z, wr.w};
            #pragma unroll
            for (int i = 0; i < 4; i++)
                #pragma unroll
                for (int j = 0; j < 4; j++)
                    acc[i][j] += a4[i] * w4[j];
        }
        __syncthreads();
    }

    #pragma unroll
    for (int i = 0; i < 4; i++) {
        int row = rowBase + ty * 4 + i;
        #pragma unroll
        for (int j = 0; j < 4; j++) {
            int col = colBase + tx * 4 + j;
            float v = acc[i][j];
            if (EPI == 3) v += bias[col];
            if (EPI == 1 || EPI == 3) v = fmaxf(v, 0.f);
            C[(size_t)row * Ncols + col] = v;
        }
    }
}

// ---------------- batched adjacency GEMM with fused mask+diag+relu epilogue ----------
// C[b][i,:] = (i<cnt[b]) * relu( Adj[b][i,:] @ Bm[b] + Bm[b][i,:] )
// K == Mr (square adjacency). Mr % 64 == 0, Ncols % 64 == 0.
__global__ void __launch_bounds__(256) gemm_adj_k(
    const float* __restrict__ Aall, const float* __restrict__ Ball,
    float* __restrict__ Call, int Mr, int Ncols, const int* __restrict__ cnt)
{
    const int b = blockIdx.z;
    const float* A  = Aall + (size_t)b * Mr * Mr;
    const float* Bm = Ball + (size_t)b * Mr * Ncols;
    float*       C  = Call + (size_t)b * Mr * Ncols;
    const int K = Mr;

    __shared__ float As[16][68];
    __shared__ float Ws[16][68];
    const int tid = threadIdx.x;
    const int tx = tid & 15, ty = tid >> 4;
    const int rowBase = blockIdx.y * 64;
    const int colBase = blockIdx.x * 64;
    const int a_r  = tid >> 2;
    const int a_k4 = (tid & 3) * 4;
    const int w_k  = tid >> 4;
    const int w_c4 = (tid & 15) * 4;

    float acc[4][4] = {};

    for (int k0 = 0; k0 < K; k0 += 16) {
        float4 av = *(const float4*)(A + (size_t)(rowBase + a_r) * K + k0 + a_k4);
        As[a_k4 + 0][a_r] = av.x;
        As[a_k4 + 1][a_r] = av.y;
        As[a_k4 + 2][a_r] = av.z;
        As[a_k4 + 3][a_r] = av.w;
        float4 wv = *(const float4*)(Bm + (size_t)(k0 + w_k) * Ncols + colBase + w_c4);
        *(float4*)&Ws[w_k][w_c4] = wv;
        __syncthreads();
        #pragma unroll
        for (int kk = 0; kk < 16; kk++) {
            float4 ar = *(const float4*)&As[kk][ty * 4];
            float4 wr = *(const float4*)&Ws[kk][tx * 4];
            float a4[4] = {ar.x, ar.y, ar.z, ar.w};
            float w4[4] = {wr.x, wr.y, wr.z, wr.w};
            #pragma unroll
            for (int i = 0; i < 4; i++)
                #pragma unroll
                for (int j = 0; j < 4; j++)
                    acc[i][j] += a4[i] * w4[j];
        }
        __syncthreads();
    }

    const int c = cnt[b];
    #pragma unroll
    for (int i = 0; i < 4; i++) {
        int row = rowBase + ty * 4 + i;
        float live = (row < c) ? 1.f : 0.f;
        #pragma unroll
        for (int j = 0; j < 4; j++) {
            int col = colBase + tx * 4 + j;
            float v = acc[i][j] + Bm[(size_t)row * Ncols + col]; // + diag(mask) term
            C[(size_t)row * Ncols + col] = live * fmaxf(v, 0.f);
        }
    }
}

// ---------------- elementwise / gather kernels ----------------

// Xm[b,n,:] = node_features[b,n,:] * (n < num_obj[b])
__global__ void k_mask_x(const float* __restrict__ nf, const int* __restrict__ nobj,
                         float* __restrict__ Xm)
{
    int bn = blockIdx.x;              // B*N blocks, 128 threads (DN/4 float4s)
    int b = bn >> 7, n = bn & 127;
    const float4* src = (const float4*)(nf + (size_t)bn * DNc);
    float4* dst = (float4*)(Xm + (size_t)bn * DNc);
    float4 v;
    if (n < nobj[b]) v = src[threadIdx.x];
    else             v = make_float4(0.f, 0.f, 0.f, 0.f);
    dst[threadIdx.x] = v;
}

// Eg[b,m,:] = edge_features[b, src, dst, :] * (m < num_edges[b])
__global__ void k_gather_eg(const float* __restrict__ ef, const int* __restrict__ eidx,
                            const int* __restrict__ nedg, float* __restrict__ Eg)
{
    int bm = blockIdx.x;              // B*M blocks, 64 threads (DE/4)
    int b = bm >> 10, m = bm & 1023;
    float4 v;
    if (m < nedg[b]) {
        int s = eidx[b * 2 * Mc + m];
        int d = eidx[b * 2 * Mc + Mc + m];
        const float4* src = (const float4*)(ef + (((size_t)b * Nc + s) * Nc + d) * DEc);
        v = src[threadIdx.x];
    } else {
        v = make_float4(0.f, 0.f, 0.f, 0.f);
    }
    ((float4*)(Eg + (size_t)bm * DEc))[threadIdx.x] = v;
}

// pairE[b,k,:] = edge_features[b, p0, p1, :]
__global__ void k_gather_pair(const float* __restrict__ ef, const int* __restrict__ opair,
                              float* __restrict__ pairE)
{
    int bk = blockIdx.x;              // B*P blocks, 64 threads
    int b = bk >> 9, k = bk & 511;
    int p0 = opair[(b * Pc + k) * 2 + 0];
    int p1 = opair[(b * Pc + k) * 2 + 1];
    const float4* src = (const float4*)(ef + (((size_t)b * Nc + p0) * Nc + p1) * DEc);
    ((float4*)(pairE + (size_t)bk * DEc))[threadIdx.x] = src[threadIdx.x];
}

// agg[b,n,:] = sum_{m : src[b,m]==n} g[b,m,:]   (deterministic scan, no atomics)
__global__ void k_agg(const int* __restrict__ eidx, const float* __restrict__ g,
                      float* __restrict__ agg)
{
    __shared__ int ssrc[Mc];
    int bn = blockIdx.x;              // B*N blocks, 128 threads (WE channels)
    int b = bn >> 7, n = bn & 127;
    for (int i = threadIdx.x; i < Mc; i += 128) ssrc[i] = eidx[b * 2 * Mc + i];
    __syncthreads();
    const float* gb = g + (size_t)b * Mc * WEc;
    float acc = 0.f;
    for (int m = 0; m < Mc; m++)
        if (ssrc[m] == n) acc += gb[(size_t)m * WEc + threadIdx.x];
    agg[(size_t)bn * WEc + threadIdx.x] = acc;
}

// ci[b,k,:] = [ h[p0]+h[p1] | agg[p0]*nm0+agg[p1]*nm1 | relu(Xp[p0]+Xp[p1]) | eQ[b,k] ]
__global__ void k_build_ci(const int* __restrict__ opair, const int* __restrict__ nobj,
                           const float* __restrict__ h, const float* __restrict__ agg,
                           const float* __restrict__ Xp, const float* __restrict__ eQ,
                           float* __restrict__ ci)
{
    int bk = blockIdx.x;              // B*P blocks, 128 threads
    int b = bk >> 9, k = bk & 511;
    int p0 = opair[(b * Pc + k) * 2 + 0];
    int p1 = opair[(b * Pc + k) * 2 + 1];
    int no = nobj[b];
    float nm0 = (p0 < no) ? 1.f : 0.f;
    float nm1 = (p1 < no) ? 1.f : 0.f;
    int c = threadIdx.x;
    const float* hb = h   + (size_t)b * Nc * WNc;
    const float* ab = agg + (size_t)b * Nc * WEc;
    const float* xb = Xp  + (size_t)b * Nc * WNc;
    float* co = ci + (size_t)bk * CI;
    co[c]           = hb[(size_t)p0 * WNc + c] + hb[(size_t)p1 * WNc + c];
    co[128 + c]     = ab[(size_t)p0 * WEc + c] * nm0 + ab[(size_t)p1 * WEc + c] * nm1;
    co[256 + c]     = fmaxf(xb[(size_t)p0 * WNc + c] + xb[(size_t)p1 * WNc + c], 0.f);
    co[384 + c]     = eQ[(size_t)bk * WEc + c];
}

// out[row, :OUT] = hid[row, :] @ W2 + b2   (small-N output layer)
__global__ void k_mlp2(const float* __restrict__ hid, const float* __restrict__ W2,
                       const float* __restrict__ b2, float* __restrict__ out, int OUT)
{
    __shared__ float sh[HIDc];
    int bk = blockIdx.x;              // B*P blocks, 64 threads
    const float* hr = hid + (size_t)bk * HIDc;
    for (int i = threadIdx.x; i < HIDc; i += 64) sh[i] = hr[i];
    __syncthreads();
    int o = threadIdx.x;
    if (o < OUT) {
        float acc = b2[o];
        #pragma unroll 4
        for (int kk = 0; kk < HIDc; kk++) acc += sh[kk] * W2[kk * OUT + o];
        out[(size_t)bk * OUT + o] = acc;
    }
}

// ---------------- launch ----------------
extern "C" void kernel_launch(void* const* d_in, const int* in_sizes, int n_in,
                              void* d_out, int out_size)
{
    const float* nf    = (const float*)d_in[0];
    const float* ef    = (const float*)d_in[1];
    const float* adj   = (const float*)d_in[2];
    const float* ladj  = (const float*)d_in[3];
    const int*   eidx  = (const int*)d_in[4];
    const int*   opair = (const int*)d_in[5];
    const int*   nobj  = (const int*)d_in[6];
    const int*   nedg  = (const int*)d_in[7];
    const float* Wn    = (const float*)d_in[8];
    const float* We    = (const float*)d_in[9];
    const float* Wn2   = (const float*)d_in[10];
    const float* We2   = (const float*)d_in[11];
    const float* scrW1 = (const float*)d_in[12];
    const float* scrb1 = (const float*)d_in[13];
    const float* scrW2 = (const float*)d_in[14];
    const float* scrb2 = (const float*)d_in[15];
    const float* lrW1  = (const float*)d_in[16];
    const float* lrb1  = (const float*)d_in[17];
    const float* lrW2  = (const float*)d_in[18];
    const float* lrb2  = (const float*)d_in[19];
    const float* mrW1  = (const float*)d_in[20];
    const float* mrb1  = (const float*)d_in[21];
    const float* mrW2  = (const float*)d_in[22];
    const float* mrb2  = (const float*)d_in[23];
    float* out = (float*)d_out;

    float* S = nullptr;
    cudaGetSymbolAddress((void**)&S, d_scratch);  // query only; capture-safe
    float* Xm    = S + OFF_XM;
    float* XWn   = S + OFF_XWN;
    float* Xp    = S + OFF_XP;
    float* h     = S + OFF_H;
    float* Eg    = S + OFF_EG;
    float* EgWe  = S + OFF_EGWE;
    float* g     = S + OFF_G;
    float* agg   = S + OFF_AGG;
    float* pairE = S + OFF_PAIRE;
    float* eQ    = S + OFF_EQ;
    float* ci    = S + OFF_CI;
    float* hid   = S + OFF_HID;

    // node path
    k_mask_x<<<Bc * Nc, 128>>>(nf, nobj, Xm);
    gemm_k<0><<<dim3(WNc / 64, (Bc * Nc) / 64), 256>>>(Xm, Wn,  XWn, Bc * Nc, DNc, WNc, nullptr);
    gemm_k<0><<<dim3(WNc / 64, (Bc * Nc) / 64), 256>>>(Xm, Wn2, Xp,  Bc * Nc, DNc, WNc, nullptr);
    gemm_adj_k<<<dim3(WNc / 64, Nc / 64, Bc), 256>>>(adj, XWn, h, Nc, WNc, nobj);

    // edge / line-graph path
    k_gather_eg<<<Bc * Mc, 64>>>(ef, eidx, nedg, Eg);
    gemm_k<0><<<dim3(WEc / 64, (Bc * Mc) / 64), 256>>>(Eg, We, EgWe, Bc * Mc, DEc, WEc, nullptr);
    gemm_adj_k<<<dim3(WEc / 64, Mc / 64, Bc), 256>>>(ladj, EgWe, g, Mc, WEc, nedg);
    k_agg<<<Bc * Nc, 128>>>(eidx, g, agg);

    // pair features
    k_gather_pair<<<Bc * Pc, 64>>>(ef, opair, pairE);
    gemm_k<1><<<dim3(WEc / 64, (Bc * Pc) / 64), 256>>>(pairE, We2, eQ, Bc * Pc, DEc, WEc, nullptr);
    k_build_ci<<<Bc * Pc, 128>>>(opair, nobj, h, agg, Xp, eQ, ci);

    // heads: output layout = [lr (B,P,9) | cr (B,P,6) | mr (B,P,17)]
    const int rows = Bc * Pc;
    gemm_k<3><<<dim3(HIDc / 64, rows / 64), 256>>>(ci, lrW1, hid, rows, CI, HIDc, lrb1);
    k_mlp2<<<rows, 64>>>(hid, lrW2, lrb2, out, 9);
    gemm_k<3><<<dim3(HIDc / 64, rows / 64), 256>>>(ci, scrW1, hid, rows, CI, HIDc, scrb1);
    k_mlp2<<<rows, 64>>>(hid, scrW2, scrb2, out + (size_t)rows * 9, 6);
    gemm_k<3><<<dim3(HIDc / 64, rows / 64), 256>>>(ci, mrW1, hid, rows, CI, HIDc, mrb1);
    k_mlp2<<<rows, 64>>>(hid, mrW2, mrb2, out + (size_t)rows * 15, 17);
}

// round 5
// speedup vs baseline: 1.6802x; 1.6802x over previous
#include <cuda_runtime.h>
#include <cuda_bf16.h>
#include <cstdint>
#include <cstddef>

// ---------------- problem constants ----------------
constexpr int Bc = 16;
constexpr int Nc = 128;
constexpr int Mc = 1024;
constexpr int DNc = 512;
constexpr int DEc = 256;
constexpr int WNc = 128;
constexpr int WEc = 128;
constexpr int Pc = 512;
constexpr int HIDc = 256;
constexpr int CI = 512;       // 2*(WN+WE)
constexpr int HID3 = 3 * HIDc; // 768 (packed heads)

// ---------------- scratch (device global, no allocs) ----------------
constexpr size_t OFF_XM    = 0;
constexpr size_t OFF_XWN   = OFF_XM    + (size_t)Bc*Nc*DNc;
constexpr size_t OFF_XP    = OFF_XWN   + (size_t)Bc*Nc*WNc;
constexpr size_t OFF_H     = OFF_XP    + (size_t)Bc*Nc*WNc;
constexpr size_t OFF_EG    = OFF_H     + (size_t)Bc*Nc*WNc;
constexpr size_t OFF_EGWE  = OFF_EG    + (size_t)Bc*Mc*DEc;
constexpr size_t OFF_G     = OFF_EGWE  + (size_t)Bc*Mc*WEc;
constexpr size_t OFF_AGG   = OFF_G     + (size_t)Bc*Mc*WEc;
constexpr size_t OFF_PAIRE = OFF_AGG   + (size_t)Bc*Nc*WEc;
constexpr size_t OFF_EQ    = OFF_PAIRE + (size_t)Bc*Pc*DEc;
constexpr size_t OFF_CI    = OFF_EQ    + (size_t)Bc*Pc*WEc;
constexpr size_t OFF_HID   = OFF_CI    + (size_t)Bc*Pc*CI;         // B*P*768
constexpr size_t OFF_WCAT  = OFF_HID   + (size_t)Bc*Pc*HID3;       // 512*768
constexpr size_t OFF_BCAT  = OFF_WCAT  + (size_t)CI*HID3;          // 768
constexpr size_t SCRATCH_TOTAL = OFF_BCAT + HID3;

__device__ float d_scratch[SCRATCH_TOTAL];

// ---------------- tf32 helpers ----------------
__device__ __forceinline__ uint32_t f2tf32(float f) {
    uint32_t u;
    asm("cvt.rna.tf32.f32 %0, %1;" : "=r"(u) : "f"(f));
    return u;
}

__device__ __forceinline__ void mma_tf32(float c[4], const uint32_t a[4], const uint32_t b[2]) {
    asm volatile(
        "mma.sync.aligned.m16n8k8.row.col.f32.tf32.tf32.f32 "
        "{%0,%1,%2,%3}, {%4,%5,%6,%7}, {%8,%9}, {%0,%1,%2,%3};"
        : "+f"(c[0]), "+f"(c[1]), "+f"(c[2]), "+f"(c[3])
        : "r"(a[0]), "r"(a[1]), "r"(a[2]), "r"(a[3]), "r"(b[0]), "r"(b[1]));
}

// ---------------- tf32 tensor-core GEMM ----------------
// C[Mr,Ncols] = epi(A[Mr,K] @ W[K,Ncols]); A,W row-major fp32.
// Requires Mr%128==0, Ncols%128==0, K%32==0. EPI: 0 none, 1 relu, 3 bias+relu.
// Block tile 128x128x32, 256 threads = 8 warps (4 row x 2 col), warp tile 32x64.
template<int EPI>
__global__ void __launch_bounds__(256) gemm_tc(
    const float* __restrict__ A, const float* __restrict__ W,
    float* __restrict__ C, int Mr, int K, int Ncols,
    const float* __restrict__ bias)
{
    __shared__ uint32_t As[128][36];   // [m][k], pad 36
    __shared__ uint32_t Bs[32][132];   // [k][n], pad 132

    const int tid  = threadIdx.x;
    const int wid  = tid >> 5;
    const int lane = tid & 31;
    const int wr   = wid >> 1;          // 0..3
    const int wc   = wid & 1;           // 0..1
    const int g    = lane >> 2;         // 0..7
    const int tig  = lane & 3;          // 0..3

    const int rowBlk = blockIdx.y * 128;
    const int colBlk = blockIdx.x * 128;
    const int wrBase = wr * 32;
    const int wcBase = wc * 64;

    float acc[2][8][4];
    #pragma unroll
    for (int mt = 0; mt < 2; mt++)
        #pragma unroll
        for (int nt = 0; nt < 8; nt++)
            #pragma unroll
            for (int q = 0; q < 4; q++) acc[mt][nt][q] = 0.f;

    for (int k0 = 0; k0 < K; k0 += 32) {
        // load A tile 128x32 (4 float4 / thread), convert to tf32
        #pragma unroll
        for (int r = 0; r < 4; r++) {
            int idx = r * 256 + tid;          // 0..1023
            int row = idx >> 3;               // /8
            int c4  = (idx & 7) * 4;
            float4 v = *(const float4*)(A + (size_t)(rowBlk + row) * K + k0 + c4);
            As[row][c4 + 0] = f2tf32(v.x);
            As[row][c4 + 1] = f2tf32(v.y);
            As[row][c4 + 2] = f2tf32(v.z);
            As[row][c4 + 3] = f2tf32(v.w);
        }
        // load B tile 32x128
        #pragma unroll
        for (int r = 0; r < 4; r++) {
            int idx = r * 256 + tid;
            int row = idx >> 5;               // /32
            int c4  = (idx & 31) * 4;
            float4 v = *(const float4*)(W + (size_t)(k0 + row) * Ncols + colBlk + c4);
            Bs[row][c4 + 0] = f2tf32(v.x);
            Bs[row][c4 + 1] = f2tf32(v.y);
            Bs[row][c4 + 2] = f2tf32(v.z);
            Bs[row][c4 + 3] = f2tf32(v.w);
        }
        __syncthreads();

        #pragma unroll
        for (int ks = 0; ks < 4; ks++) {
            const int kb = ks * 8;
            uint32_t a[2][4];
            #pragma unroll
            for (int mt = 0; mt < 2; mt++) {
                int rbase = wrBase + mt * 16;
                a[mt][0] = As[rbase + g][kb + tig];
                a[mt][1] = As[rbase + g + 8][kb + tig];
                a[mt][2] = As[rbase + g][kb + tig + 4];
                a[mt][3] = As[rbase + g + 8][kb + tig + 4];
            }
            #pragma unroll
            for (int nt = 0; nt < 8; nt++) {
                uint32_t b[2];
                int col = wcBase + nt * 8 + g;
                b[0] = Bs[kb + tig][col];
                b[1] = Bs[kb + tig + 4][col];
                mma_tf32(acc[0][nt], a[0], b);
                mma_tf32(acc[1][nt], a[1], b);
            }
        }
        __syncthreads();
    }

    // epilogue (vectorized float2 stores; c layout makes pairs adjacent)
    #pragma unroll
    for (int mt = 0; mt < 2; mt++) {
        int r0 = rowBlk + wrBase + mt * 16 + g;
        int r1 = r0 + 8;
        #pragma unroll
        for (int nt = 0; nt < 8; nt++) {
            int c0 = colBlk + wcBase + nt * 8 + tig * 2;
            float v0 = acc[mt][nt][0], v1 = acc[mt][nt][1];
            float v2 = acc[mt][nt][2], v3 = acc[mt][nt][3];
            if (EPI == 3) {
                float b0 = bias[c0], b1 = bias[c0 + 1];
                v0 += b0; v1 += b1; v2 += b0; v3 += b1;
            }
            if (EPI == 1 || EPI == 3) {
                v0 = fmaxf(v0, 0.f); v1 = fmaxf(v1, 0.f);
                v2 = fmaxf(v2, 0.f); v3 = fmaxf(v3, 0.f);
            }
            *(float2*)(C + (size_t)r0 * Ncols + c0) = make_float2(v0, v1);
            *(float2*)(C + (size_t)r1 * Ncols + c0) = make_float2(v2, v3);
        }
    }
}

// ---------------- sparse adjacency aggregation ----------------
// Out[b,i,:] = (i<cnt[b]) * relu( sum_{j<cnt, Adj[i,j]!=0} Adj[i,j]*Feat[b,j,:] + Feat[b,i,:] )
// Feat rows already zero for j>=cnt. 128 channels = 128 threads.
// Deterministic: nonzeros compacted in ascending j via warp-0 ballot rounds.
template<int ROWLEN>
__global__ void __launch_bounds__(128) k_adj_sparse(
    const float* __restrict__ Adj, const float* __restrict__ Feat,
    const int* __restrict__ cntArr, float* __restrict__ Out)
{
    __shared__ float srow[ROWLEN];
    __shared__ int   sidx[ROWLEN];
    __shared__ float sval[ROWLEN];
    __shared__ int   scount;

    const int blk = blockIdx.x;
    const int b   = blk / ROWLEN;
    const int i   = blk % ROWLEN;
    const int tid = threadIdx.x;
    const int cnt = cntArr[b];

    float* outRow = Out + (size_t)blk * 128;
    if (i >= cnt) { outRow[tid] = 0.f; return; }

    const float* Arow = Adj + ((size_t)b * ROWLEN + i) * ROWLEN;
    for (int j = tid; j < ROWLEN; j += 128) srow[j] = Arow[j];
    __syncthreads();

    if (tid < 32) {
        int cn = 0;
        #pragma unroll 4
        for (int base = 0; base < ROWLEN; base += 32) {
            int j = base + tid;
            float v = srow[j];
            bool nz = (v != 0.f) && (j < cnt);
            unsigned msk = __ballot_sync(0xffffffffu, nz);
            int pos = cn + __popc(msk & ((1u << tid) - 1u));
            if (nz) { sidx[pos] = j; sval[pos] = v; }
            cn += __popc(msk);
        }
        if (tid == 0) scount = cn;
    }
    __syncthreads();

    const int n = scount;
    const float* Fb = Feat + (size_t)b * ROWLEN * 128;
    float acc = Fb[(size_t)i * 128 + tid];          // + eye * mask term
    for (int t = 0; t < n; t++)
        acc = fmaf(sval[t], Fb[(size_t)sidx[t] * 128 + tid], acc);
    outRow[tid] = fmaxf(acc, 0.f);
}

// ---------------- elementwise / gather kernels ----------------
__global__ void k_mask_x(const float* __restrict__ nf, const int* __restrict__ nobj,
                         float* __restrict__ Xm)
{
    int bn = blockIdx.x;
    int b = bn >> 7, n = bn & 127;
    float4 v;
    if (n < nobj[b]) v = ((const float4*)(nf + (size_t)bn * DNc))[threadIdx.x];
    else             v = make_float4(0.f, 0.f, 0.f, 0.f);
    ((float4*)(Xm + (size_t)bn * DNc))[threadIdx.x] = v;
}

__global__ void k_gather_eg(const float* __restrict__ ef, const int* __restrict__ eidx,
                            const int* __restrict__ nedg, float* __restrict__ Eg)
{
    int bm = blockIdx.x;
    int b = bm >> 10, m = bm & 1023;
    float4 v;
    if (m < nedg[b]) {
        int s = eidx[b * 2 * Mc + m];
        int d = eidx[b * 2 * Mc + Mc + m];
        v = ((const float4*)(ef + (((size_t)b * Nc + s) * Nc + d) * DEc))[threadIdx.x];
    } else {
        v = make_float4(0.f, 0.f, 0.f, 0.f);
    }
    ((float4*)(Eg + (size_t)bm * DEc))[threadIdx.x] = v;
}

__global__ void k_gather_pair(const float* __restrict__ ef, const int* __restrict__ opair,
                              float* __restrict__ pairE)
{
    int bk = blockIdx.x;
    int b = bk >> 9, k = bk & 511;
    int p0 = opair[(b * Pc + k) * 2 + 0];
    int p1 = opair[(b * Pc + k) * 2 + 1];
    ((float4*)(pairE + (size_t)bk * DEc))[threadIdx.x] =
        ((const float4*)(ef + (((size_t)b * Nc + p0) * Nc + p1) * DEc))[threadIdx.x];
}

// agg[b,n,:] = sum_{m : src[b,m]==n} g[b,m,:]  (deterministic ascending scan)
__global__ void k_agg(const int* __restrict__ eidx, const float* __restrict__ g,
                      float* __restrict__ agg)
{
    __shared__ int ssrc[Mc];
    int bn = blockIdx.x;
    int b = bn >> 7, n = bn & 127;
    for (int i = threadIdx.x; i < Mc; i += 128) ssrc[i] = eidx[b * 2 * Mc + i];
    __syncthreads();
    const float* gb = g + (size_t)b * Mc * WEc;
    float acc = 0.f;
    for (int m = 0; m < Mc; m++)
        if (ssrc[m] == n) acc += gb[(size_t)m * WEc + threadIdx.x];
    agg[(size_t)bn * WEc + threadIdx.x] = acc;
}

__global__ void k_build_ci(const int* __restrict__ opair, const int* __restrict__ nobj,
                           const float* __restrict__ h, const float* __restrict__ agg,
                           const float* __restrict__ Xp, const float* __restrict__ eQ,
                           float* __restrict__ ci)
{
    int bk = blockIdx.x;
    int b = bk >> 9, k = bk & 511;
    int p0 = opair[(b * Pc + k) * 2 + 0];
    int p1 = opair[(b * Pc + k) * 2 + 1];
    int no = nobj[b];
    float nm0 = (p0 < no) ? 1.f : 0.f;
    float nm1 = (p1 < no) ? 1.f : 0.f;
    int c = threadIdx.x;
    const float* hb = h   + (size_t)b * Nc * WNc;
    const float* ab = agg + (size_t)b * Nc * WEc;
    const float* xb = Xp  + (size_t)b * Nc * WNc;
    float* co = ci + (size_t)bk * CI;
    co[c]       = hb[(size_t)p0 * WNc + c] + hb[(size_t)p1 * WNc + c];
    co[128 + c] = ab[(size_t)p0 * WEc + c] * nm0 + ab[(size_t)p1 * WEc + c] * nm1;
    co[256 + c] = fmaxf(xb[(size_t)p0 * WNc + c] + xb[(size_t)p1 * WNc + c], 0.f);
    co[384 + c] = eQ[(size_t)bk * WEc + c];
}

// pack [lrW1 | scrW1 | mrW1] -> Wcat[512][768], biases -> bcat[768]
__global__ void k_pack(const float* __restrict__ lrW1, const float* __restrict__ scrW1,
                       const float* __restrict__ mrW1, const float* __restrict__ lrb1,
                       const float* __restrict__ scrb1, const float* __restrict__ mrb1,
                       float* __restrict__ Wcat, float* __restrict__ bcat)
{
    int idx = blockIdx.x * 256 + threadIdx.x;
    if (idx < CI * HIDc) {
        int k = idx >> 8, c = idx & 255;
        Wcat[(size_t)k * HID3 + c]             = lrW1[idx];
        Wcat[(size_t)k * HID3 + HIDc + c]      = scrW1[idx];
        Wcat[(size_t)k * HID3 + 2 * HIDc + c]  = mrW1[idx];
    }
    if (blockIdx.x == 0 && threadIdx.x < HIDc) {
        int i = threadIdx.x;
        bcat[i]             = lrb1[i];
        bcat[HIDc + i]      = scrb1[i];
        bcat[2 * HIDc + i]  = mrb1[i];
    }
}

// out[row, :OUT] = hid[row, off:off+HID] @ W2 + b2   (small-N output layer)
__global__ void k_mlp2(const float* __restrict__ hid, int stride, int off,
                       const float* __restrict__ W2, const float* __restrict__ b2,
                       float* __restrict__ out, int OUT)
{
    __shared__ float sh[HIDc];
    int bk = blockIdx.x;
    const float* hr = hid + (size_t)bk * stride + off;
    for (int i = threadIdx.x; i < HIDc; i += 64) sh[i] = hr[i];
    __syncthreads();
    int o = threadIdx.x;
    if (o < OUT) {
        float acc = b2[o];
        #pragma unroll 4
        for (int kk = 0; kk < HIDc; kk++) acc += sh[kk] * W2[kk * OUT + o];
        out[(size_t)bk * OUT + o] = acc;
    }
}

// ---------------- launch ----------------
extern "C" void kernel_launch(void* const* d_in, const int* in_sizes, int n_in,
                              void* d_out, int out_size)
{
    const float* nf    = (const float*)d_in[0];
    const float* ef    = (const float*)d_in[1];
    const float* adj   = (const float*)d_in[2];
    const float* ladj  = (const float*)d_in[3];
    const int*   eidx  = (const int*)d_in[4];
    const int*   opair = (const int*)d_in[5];
    const int*   nobj  = (const int*)d_in[6];
    const int*   nedg  = (const int*)d_in[7];
    const float* Wn    = (const float*)d_in[8];
    const float* We    = (const float*)d_in[9];
    const float* Wn2   = (const float*)d_in[10];
    const float* We2   = (const float*)d_in[11];
    const float* scrW1 = (const float*)d_in[12];
    const float* scrb1 = (const float*)d_in[13];
    const float* scrW2 = (const float*)d_in[14];
    const float* scrb2 = (const float*)d_in[15];
    const float* lrW1  = (const float*)d_in[16];
    const float* lrb1  = (const float*)d_in[17];
    const float* lrW2  = (const float*)d_in[18];
    const float* lrb2  = (const float*)d_in[19];
    const float* mrW1  = (const float*)d_in[20];
    const float* mrb1  = (const float*)d_in[21];
    const float* mrW2  = (const float*)d_in[22];
    const float* mrb2  = (const float*)d_in[23];
    float* out = (float*)d_out;

    float* S = nullptr;
    cudaGetSymbolAddress((void**)&S, d_scratch);
    float* Xm    = S + OFF_XM;
    float* XWn   = S + OFF_XWN;
    float* Xp    = S + OFF_XP;
    float* h     = S + OFF_H;
    float* Eg    = S + OFF_EG;
    float* EgWe  = S + OFF_EGWE;
    float* g     = S + OFF_G;
    float* agg   = S + OFF_AGG;
    float* pairE = S + OFF_PAIRE;
    float* eQ    = S + OFF_EQ;
    float* ci    = S + OFF_CI;
    float* hid   = S + OFF_HID;
    float* Wcat  = S + OFF_WCAT;
    float* bcat  = S + OFF_BCAT;

    // pack head weights (independent of data path, launch first)
    k_pack<<<(CI * HIDc + 255) / 256, 256>>>(lrW1, scrW1, mrW1, lrb1, scrb1, mrb1, Wcat, bcat);

    // node path
    k_mask_x<<<Bc * Nc, 128>>>(nf, nobj, Xm);
    gemm_tc<0><<<dim3(WNc / 128, (Bc * Nc) / 128), 256>>>(Xm, Wn,  XWn, Bc * Nc, DNc, WNc, nullptr);
    gemm_tc<0><<<dim3(WNc / 128, (Bc * Nc) / 128), 256>>>(Xm, Wn2, Xp,  Bc * Nc, DNc, WNc, nullptr);
    k_adj_sparse<Nc><<<Bc * Nc, 128>>>(adj, XWn, nobj, h);

    // edge / line-graph path (sparse line adjacency)
    k_gather_eg<<<Bc * Mc, 64>>>(ef, eidx, nedg, Eg);
    gemm_tc<0><<<dim3(WEc / 128, (Bc * Mc) / 128), 256>>>(Eg, We, EgWe, Bc * Mc, DEc, WEc, nullptr);
    k_adj_sparse<Mc><<<Bc * Mc, 128>>>(ladj, EgWe, nedg, g);
    k_agg<<<Bc * Nc, 128>>>(eidx, g, agg);

    // pair features
    k_gather_pair<<<Bc * Pc, 64>>>(ef, opair, pairE);
    gemm_tc<1><<<dim3(WEc / 128, (Bc * Pc) / 128), 256>>>(pairE, We2, eQ, Bc * Pc, DEc, WEc, nullptr);
    k_build_ci<<<Bc * Pc, 128>>>(opair, nobj, h, agg, Xp, eQ, ci);

    // fused heads: hid[8192, 768] = relu(ci @ Wcat + bcat)
    const int rows = Bc * Pc;
    gemm_tc<3><<<dim3(HID3 / 128, rows / 128), 256>>>(ci, Wcat, hid, rows, CI, HID3, bcat);

    // output layout = [lr (B,P,9) | cr (B,P,6) | mr (B,P,17)]
    k_mlp2<<<rows, 64>>>(hid, HID3, 0,        lrW2,  lrb2,  out, 9);
    k_mlp2<<<rows, 64>>>(hid, HID3, HIDc,     scrW2, scrb2, out + (size_t)rows * 9, 6);
    k_mlp2<<<rows, 64>>>(hid, HID3, 2 * HIDc, mrW2,  mrb2,  out + (size_t)rows * 15, 17);
}

// round 8
// speedup vs baseline: 2.4633x; 1.4660x over previous
#include <cuda_runtime.h>
#include <cuda_bf16.h>
#include <cstdint>
#include <cstddef>

// ---------------- problem constants ----------------
constexpr int Bc = 16;
constexpr int Nc = 128;
constexpr int Mc = 1024;
constexpr int DNc = 512;
constexpr int DEc = 256;
constexpr int WNc = 128;
constexpr int WEc = 128;
constexpr int Pc = 512;
constexpr int HIDc = 256;
constexpr int CI = 512;        // 2*(WN+WE)
constexpr int HID3 = 3 * HIDc; // 768

// ---------------- scratch (device global, no allocs) ----------------
constexpr size_t OFF_XM    = 0;
constexpr size_t OFF_XWCAT = OFF_XM    + (size_t)Bc*Nc*DNc;    // 2048x256
constexpr size_t OFF_H     = OFF_XWCAT + (size_t)Bc*Nc*256;
constexpr size_t OFF_EG    = OFF_H     + (size_t)Bc*Nc*WNc;
constexpr size_t OFF_EGWE  = OFF_EG    + (size_t)Bc*Mc*DEc;
constexpr size_t OFF_G     = OFF_EGWE  + (size_t)Bc*Mc*WEc;
constexpr size_t OFF_AGG   = OFF_G     + (size_t)Bc*Mc*WEc;
constexpr size_t OFF_PAIRE = OFF_AGG   + (size_t)Bc*Nc*WEc;
constexpr size_t OFF_EQ    = OFF_PAIRE + (size_t)Bc*Pc*DEc;
constexpr size_t OFF_CI    = OFF_EQ    + (size_t)Bc*Pc*WEc;
constexpr size_t OFF_HID   = OFF_CI    + (size_t)Bc*Pc*CI;
constexpr size_t OFF_WNCAT = OFF_HID   + (size_t)Bc*Pc*HID3;   // 512x256
constexpr size_t OFF_WCAT  = OFF_WNCAT + (size_t)DNc*256;      // 512x768
constexpr size_t OFF_BCAT  = OFF_WCAT  + (size_t)CI*HID3;
constexpr size_t SCRATCH_TOTAL = OFF_BCAT + HID3;

__device__ float d_scratch[SCRATCH_TOTAL];

// ---------------- tf32 / cp.async helpers ----------------
__device__ __forceinline__ uint32_t f2tf32(float f) {
    uint32_t u;
    asm("cvt.rna.tf32.f32 %0, %1;" : "=r"(u) : "f"(f));
    return u;
}
__device__ __forceinline__ void mma_tf32(float c[4], const uint32_t a[4], const uint32_t b[2]) {
    asm volatile(
        "mma.sync.aligned.m16n8k8.row.col.f32.tf32.tf32.f32 "
        "{%0,%1,%2,%3}, {%4,%5,%6,%7}, {%8,%9}, {%0,%1,%2,%3};"
        : "+f"(c[0]), "+f"(c[1]), "+f"(c[2]), "+f"(c[3])
        : "r"(a[0]), "r"(a[1]), "r"(a[2]), "r"(a[3]), "r"(b[0]), "r"(b[1]));
}
__device__ __forceinline__ void cp16(void* s, const void* g) {
    uint32_t sa = (uint32_t)__cvta_generic_to_shared(s);
    asm volatile("cp.async.cg.shared.global [%0], [%1], 16;" :: "r"(sa), "l"(g));
}

// ---------------- pipelined tf32 GEMM device function ----------------
// C[.,Ncols] tile (rowBlk,colBlk) 128x128 = epi(A[.,K] @ W[K,Ncols])
// 256 threads, K-step 16, 2-stage cp.async pipeline. K % 16 == 0.
constexpr int AS_STR = 20;   // 16 + 4 pad
constexpr int BS_STR = 136;  // 128 + 8 pad

struct SmemGemm {
    float As[2][128][AS_STR];
    float Bs[2][16][BS_STR];
};  // 37,888 bytes

template<int EPI>  // 0 none, 1 relu, 3 bias+relu
__device__ __forceinline__ void gemm_dev(SmemGemm& S,
    const float* __restrict__ A, const float* __restrict__ W, float* __restrict__ C,
    int K, int Ncols, int rowBlk, int colBlk, const float* __restrict__ bias)
{
    const int tid  = threadIdx.x;
    const int wid  = tid >> 5, lane = tid & 31;
    const int wr   = wid >> 1, wc = wid & 1;
    const int g    = lane >> 2, tig = lane & 3;
    const int wrBase = wr * 32, wcBase = wc * 64;

    const int a_row = tid >> 2;         // 0..63 (+64)
    const int a_c4  = (tid & 3) * 4;    // 0,4,8,12
    const int b_row = tid >> 5;         // 0..7 (+8)
    const int b_c4  = (tid & 31) * 4;   // 0..124

    float acc[2][8][4];
    #pragma unroll
    for (int mt = 0; mt < 2; mt++)
        #pragma unroll
        for (int nt = 0; nt < 8; nt++)
            #pragma unroll
            for (int q = 0; q < 4; q++) acc[mt][nt][q] = 0.f;

    const int KT = K >> 4;

    // prologue: stage 0
    {
        cp16(&S.As[0][a_row][a_c4],      A + (size_t)(rowBlk + a_row) * K + a_c4);
        cp16(&S.As[0][a_row + 64][a_c4], A + (size_t)(rowBlk + a_row + 64) * K + a_c4);
        cp16(&S.Bs[0][b_row][b_c4],      W + (size_t)b_row * Ncols + colBlk + b_c4);
        cp16(&S.Bs[0][b_row + 8][b_c4],  W + (size_t)(b_row + 8) * Ncols + colBlk + b_c4);
        asm volatile("cp.async.commit_group;");
    }

    for (int kt = 0; kt < KT; kt++) {
        const int cur = kt & 1;
        if (kt + 1 < KT) {
            const int nxt = cur ^ 1;
            const int k0 = (kt + 1) << 4;
            cp16(&S.As[nxt][a_row][a_c4],      A + (size_t)(rowBlk + a_row) * K + k0 + a_c4);
            cp16(&S.As[nxt][a_row + 64][a_c4], A + (size_t)(rowBlk + a_row + 64) * K + k0 + a_c4);
            cp16(&S.Bs[nxt][b_row][b_c4],      W + (size_t)(k0 + b_row) * Ncols + colBlk + b_c4);
            cp16(&S.Bs[nxt][b_row + 8][b_c4],  W + (size_t)(k0 + b_row + 8) * Ncols + colBlk + b_c4);
            asm volatile("cp.async.commit_group;");
            asm volatile("cp.async.wait_group 1;");
        } else {
            asm volatile("cp.async.wait_group 0;");
        }
        __syncthreads();

        #pragma unroll
        for (int ks = 0; ks < 2; ks++) {
            const int kb = ks * 8;
            uint32_t afr[2][4];
            #pragma unroll
            for (int mt = 0; mt < 2; mt++) {
                int rb = wrBase + mt * 16;
                afr[mt][0] = f2tf32(S.As[cur][rb + g    ][kb + tig]);
                afr[mt][1] = f2tf32(S.As[cur][rb + g + 8][kb + tig]);
                afr[mt][2] = f2tf32(S.As[cur][rb + g    ][kb + tig + 4]);
                afr[mt][3] = f2tf32(S.As[cur][rb + g + 8][kb + tig + 4]);
            }
            #pragma unroll
            for (int nt = 0; nt < 8; nt++) {
                uint32_t bfr[2];
                int col = wcBase + nt * 8 + g;
                bfr[0] = f2tf32(S.Bs[cur][kb + tig    ][col]);
                bfr[1] = f2tf32(S.Bs[cur][kb + tig + 4][col]);
                mma_tf32(acc[0][nt], afr[0], bfr);
                mma_tf32(acc[1][nt], afr[1], bfr);
            }
        }
        __syncthreads();
    }

    // epilogue
    #pragma unroll
    for (int mt = 0; mt < 2; mt++) {
        int r0 = rowBlk + wrBase + mt * 16 + g;
        int r1 = r0 + 8;
        #pragma unroll
        for (int nt = 0; nt < 8; nt++) {
            int c0 = colBlk + wcBase + nt * 8 + tig * 2;
            float v0 = acc[mt][nt][0], v1 = acc[mt][nt][1];
            float v2 = acc[mt][nt][2], v3 = acc[mt][nt][3];
            if (EPI == 3) {
                float b0 = bias[c0], b1 = bias[c0 + 1];
                v0 += b0; v1 += b1; v2 += b0; v3 += b1;
            }
            if (EPI == 1 || EPI == 3) {
                v0 = fmaxf(v0, 0.f); v1 = fmaxf(v1, 0.f);
                v2 = fmaxf(v2, 0.f); v3 = fmaxf(v3, 0.f);
            }
            *(float2*)(C + (size_t)r0 * Ncols + c0) = make_float2(v0, v1);
            *(float2*)(C + (size_t)r1 * Ncols + c0) = make_float2(v2, v3);
        }
    }
}

// ---------------- L2: batched pre-GEMMs (one launch, 224 blocks) ----------------
__global__ void __launch_bounds__(256) k_gemm3(
    const float* __restrict__ Xm, const float* __restrict__ Wncat, float* __restrict__ XWcat,
    const float* __restrict__ Eg, const float* __restrict__ We, float* __restrict__ EgWe,
    const float* __restrict__ pairE, const float* __restrict__ We2, float* __restrict__ eQ)
{
    __shared__ SmemGemm S;
    int id = blockIdx.x;
    if (id < 32) {
        gemm_dev<0>(S, Xm, Wncat, XWcat, 512, 256, (id >> 1) * 128, (id & 1) * 128, nullptr);
    } else if (id < 160) {
        gemm_dev<0>(S, Eg, We, EgWe, 256, 128, (id - 32) * 128, 0, nullptr);
    } else {
        gemm_dev<1>(S, pairE, We2, eQ, 256, 128, (id - 160) * 128, 0, nullptr);
    }
}

// ---------------- L6: heads GEMM (384 blocks) ----------------
__global__ void __launch_bounds__(256) k_gemm_heads(
    const float* __restrict__ ci, const float* __restrict__ Wcat,
    const float* __restrict__ bcat, float* __restrict__ hid)
{
    __shared__ SmemGemm S;
    int id = blockIdx.x;
    gemm_dev<3>(S, ci, Wcat, hid, 512, 768, (id / 6) * 128, (id % 6) * 128, bcat);
}

// ---------------- L1: fused prep (gathers + weight packing) ----------------
constexpr int PREP_MASK_END = Bc * Nc;                 // 2048
constexpr int PREP_EG_END   = PREP_MASK_END + Bc * Mc; // 18432
constexpr int PREP_PAIR_END = PREP_EG_END + Bc * Pc;   // 26624
constexpr int PREP_PW_END   = PREP_PAIR_END + (DNc * WNc) / 128;  // +512 (Wncat: 512x128 elems)
constexpr int PREP_TOTAL    = PREP_PW_END + (CI * HIDc) / 128;    // +1024 (Wcat: 512x256 elems)

__global__ void __launch_bounds__(128) k_prep(
    const float* __restrict__ nf, const int* __restrict__ nobj, float* __restrict__ Xm,
    const float* __restrict__ ef, const int* __restrict__ eidx, const int* __restrict__ nedg,
    float* __restrict__ Eg, const int* __restrict__ opair, float* __restrict__ pairE,
    const float* __restrict__ Wn, const float* __restrict__ Wn2, float* __restrict__ Wncat,
    const float* __restrict__ lrW1, const float* __restrict__ scrW1, const float* __restrict__ mrW1,
    const float* __restrict__ lrb1, const float* __restrict__ scrb1, const float* __restrict__ mrb1,
    float* __restrict__ Wcat, float* __restrict__ bcat)
{
    const int blk = blockIdx.x, tid = threadIdx.x;
    if (blk < PREP_MASK_END) {
        int b = blk >> 7, n = blk & 127;
        float4 v = make_float4(0.f, 0.f, 0.f, 0.f);
        if (n < nobj[b]) v = ((const float4*)(nf + (size_t)blk * DNc))[tid];
        ((float4*)(Xm + (size_t)blk * DNc))[tid] = v;
    } else if (blk < PREP_EG_END) {
        int bm = blk - PREP_MASK_END;
        int b = bm >> 10, m = bm & 1023;
        float2 v = make_float2(0.f, 0.f);
        if (m < nedg[b]) {
            int s = eidx[b * 2 * Mc + m];
            int d = eidx[b * 2 * Mc + Mc + m];
            v = ((const float2*)(ef + (((size_t)b * Nc + s) * Nc + d) * DEc))[tid];
        }
        ((float2*)(Eg + (size_t)bm * DEc))[tid] = v;
    } else if (blk < PREP_PAIR_END) {
        int bk = blk - PREP_EG_END;
        int b = bk >> 9, k = bk & 511;
        int p0 = opair[(b * Pc + k) * 2 + 0];
        int p1 = opair[(b * Pc + k) * 2 + 1];
        ((float2*)(pairE + (size_t)bk * DEc))[tid] =
            ((const float2*)(ef + (((size_t)b * Nc + p0) * Nc + p1) * DEc))[tid];
    } else if (blk < PREP_PW_END) {
        int idx = (blk - PREP_PAIR_END) * 128 + tid;   // over 512*128 exactly
        int k = idx >> 7, c = idx & 127;
        Wncat[(size_t)k * 256 + c]       = Wn[idx];
        Wncat[(size_t)k * 256 + 128 + c] = Wn2[idx];
    } else {
        int idx = (blk - PREP_PW_END) * 128 + tid;     // over 512*256 exactly
        int k = idx >> 8, c = idx & 255;
        Wcat[(size_t)k * HID3 + c]             = lrW1[idx];
        Wcat[(size_t)k * HID3 + HIDc + c]      = scrW1[idx];
        Wcat[(size_t)k * HID3 + 2 * HIDc + c]  = mrW1[idx];
        if (blk == PREP_PW_END) {
            for (int i = tid; i < HIDc; i += 128) {
                bcat[i]             = lrb1[i];
                bcat[HIDc + i]      = scrb1[i];
                bcat[2 * HIDc + i]  = mrb1[i];
            }
        }
    }
}

// ---------------- L3: fused sparse adjacency (node + line graph) ----------------
__device__ __forceinline__ void adj_dev(
    const float* __restrict__ Adj, const float* __restrict__ Feat,
    const int* __restrict__ cntArr, float* __restrict__ Out,
    int blk, int ROWLEN, int featStride,
    float* srow, int* sidx, float* sval, int* scount)
{
    const int b   = blk / ROWLEN;
    const int i   = blk % ROWLEN;
    const int tid = threadIdx.x;
    const int cnt = cntArr[b];

    float* outRow = Out + (size_t)blk * 128;
    if (i >= cnt) { outRow[tid] = 0.f; return; }

    const float* Arow = Adj + ((size_t)b * ROWLEN + i) * ROWLEN;
    for (int j = tid; j < ROWLEN; j += 128) srow[j] = Arow[j];
    __syncthreads();

    if (tid < 32) {
        int cn = 0;
        for (int base = 0; base < ROWLEN; base += 32) {
            int j = base + tid;
            float v = srow[j];
            bool nz = (v != 0.f) && (j < cnt);
            unsigned msk = __ballot_sync(0xffffffffu, nz);
            int pos = cn + __popc(msk & ((1u << tid) - 1u));
            if (nz) { sidx[pos] = j; sval[pos] = v; }
            cn += __popc(msk);
        }
        if (tid == 0) *scount = cn;
    }
    __syncthreads();

    const int n = *scount;
    const float* Fb = Feat + (size_t)b * ROWLEN * featStride;
    float acc = Fb[(size_t)i * featStride + tid];     // + eye*mask term
    for (int t = 0; t < n; t++)
        acc = fmaf(sval[t], Fb[(size_t)sidx[t] * featStride + tid], acc);
    outRow[tid] = fmaxf(acc, 0.f);
}

__global__ void __launch_bounds__(128) k_adj(
    const float* __restrict__ adjN, const float* __restrict__ XWcat,
    const int* __restrict__ nobj, float* __restrict__ h,
    const float* __restrict__ adjM, const float* __restrict__ EgWe,
    const int* __restrict__ nedg, float* __restrict__ g)
{
    __shared__ float srow[Mc];
    __shared__ int   sidx[Mc];
    __shared__ float sval[Mc];
    __shared__ int   scount;
    int blk = blockIdx.x;
    if (blk < Bc * Nc)
        adj_dev(adjN, XWcat, nobj, h, blk, Nc, 256, srow, sidx, sval, &scount);
    else
        adj_dev(adjM, EgWe, nedg, g, blk - Bc * Nc, Mc, 128, srow, sidx, sval, &scount);
}

// ---------------- L4: scatter-add agg (deterministic scan) ----------------
__global__ void __launch_bounds__(128) k_agg(
    const int* __restrict__ eidx, const float* __restrict__ g, float* __restrict__ agg)
{
    __shared__ int ssrc[Mc];
    int bn = blockIdx.x;
    int b = bn >> 7, n = bn & 127;
    for (int i = threadIdx.x; i < Mc; i += 128) ssrc[i] = eidx[b * 2 * Mc + i];
    __syncthreads();
    const float* gb = g + (size_t)b * Mc * WEc;
    float acc = 0.f;
    for (int m = 0; m < Mc; m++)
        if (ssrc[m] == n) acc += gb[(size_t)m * WEc + threadIdx.x];
    agg[(size_t)bn * WEc + threadIdx.x] = acc;
}

// ---------------- L5: build classifier input ----------------
__global__ void __launch_bounds__(128) k_build_ci(
    const int* __restrict__ opair, const int* __restrict__ nobj,
    const float* __restrict__ h, const float* __restrict__ agg,
    const float* __restrict__ XWcat, const float* __restrict__ eQ,
    float* __restrict__ ci)
{
    int bk = blockIdx.x;
    int b = bk >> 9, k = bk & 511;
    int p0 = opair[(b * Pc + k) * 2 + 0];
    int p1 = opair[(b * Pc + k) * 2 + 1];
    int no = nobj[b];
    float nm0 = (p0 < no) ? 1.f : 0.f;
    float nm1 = (p1 < no) ? 1.f : 0.f;
    int c = threadIdx.x;
    const float* hb = h    + (size_t)b * Nc * WNc;
    const float* ab = agg  + (size_t)b * Nc * WEc;
    const float* xb = XWcat + (size_t)b * Nc * 256 + 128;   // Xp = cols [128,256)
    float* co = ci + (size_t)bk * CI;
    co[c]       = hb[(size_t)p0 * WNc + c] + hb[(size_t)p1 * WNc + c];
    co[128 + c] = ab[(size_t)p0 * WEc + c] * nm0 + ab[(size_t)p1 * WEc + c] * nm1;
    co[256 + c] = fmaxf(xb[(size_t)p0 * 256 + c] + xb[(size_t)p1 * 256 + c], 0.f);
    co[384 + c] = eQ[(size_t)bk * WEc + c];
}

// ---------------- L7: fused output layers (lr 9 | cr 6 | mr 17) ----------------
__global__ void __launch_bounds__(128) k_heads_out(
    const float* __restrict__ hid,
    const float* __restrict__ lrW2,  const float* __restrict__ lrb2,
    const float* __restrict__ scrW2, const float* __restrict__ scrb2,
    const float* __restrict__ mrW2,  const float* __restrict__ mrb2,
    float* __restrict__ out)
{
    __shared__ float sh[HID3];
    const int row = blockIdx.x, tid = threadIdx.x;
    const float* hr = hid + (size_t)row * HID3;
    for (int i = tid; i < HID3; i += 128) sh[i] = hr[i];
    __syncthreads();

    const int o    = tid >> 2;   // 0..31
    const int part = tid & 3;
    const float* W2; const float* b2; int off, OUT, oo; float* dst;
    const size_t rows = (size_t)Bc * Pc;
    if (o < 9)       { W2 = lrW2;  b2 = lrb2;  off = 0;   OUT = 9;  oo = o;      dst = out; }
    else if (o < 15) { W2 = scrW2; b2 = scrb2; off = 256; OUT = 6;  oo = o - 9;  dst = out + rows * 9; }
    else             { W2 = mrW2;  b2 = mrb2;  off = 512; OUT = 17; oo = o - 15; dst = out + rows * 15; }

    float acc = 0.f;
    const int k0 = part * 64;
    #pragma unroll 4
    for (int kk = k0; kk < k0 + 64; kk++)
        acc += sh[off + kk] * W2[kk * OUT + oo];
    acc += __shfl_xor_sync(0xffffffffu, acc, 1);
    acc += __shfl_xor_sync(0xffffffffu, acc, 2);
    if (part == 0) dst[(size_t)row * OUT + oo] = acc + b2[oo];
}

// ---------------- launch ----------------
extern "C" void kernel_launch(void* const* d_in, const int* in_sizes, int n_in,
                              void* d_out, int out_size)
{
    const float* nf    = (const float*)d_in[0];
    const float* ef    = (const float*)d_in[1];
    const float* adj   = (const float*)d_in[2];
    const float* ladj  = (const float*)d_in[3];
    const int*   eidx  = (const int*)d_in[4];
    const int*   opair = (const int*)d_in[5];
    const int*   nobj  = (const int*)d_in[6];
    const int*   nedg  = (const int*)d_in[7];
    const float* Wn    = (const float*)d_in[8];
    const float* We    = (const float*)d_in[9];
    const float* Wn2   = (const float*)d_in[10];
    const float* We2   = (const float*)d_in[11];
    const float* scrW1 = (const float*)d_in[12];
    const float* scrb1 = (const float*)d_in[13];
    const float* scrW2 = (const float*)d_in[14];
    const float* scrb2 = (const float*)d_in[15];
    const float* lrW1  = (const float*)d_in[16];
    const float* lrb1  = (const float*)d_in[17];
    const float* lrW2  = (const float*)d_in[18];
    const float* lrb2  = (const float*)d_in[19];
    const float* mrW1  = (const float*)d_in[20];
    const float* mrb1  = (const float*)d_in[21];
    const float* mrW2  = (const float*)d_in[22];
    const float* mrb2  = (const float*)d_in[23];
    float* out = (float*)d_out;

    float* S = nullptr;
    cudaGetSymbolAddress((void**)&S, d_scratch);
    float* Xm    = S + OFF_XM;
    float* XWcat = S + OFF_XWCAT;
    float* h     = S + OFF_H;
    float* Eg    = S + OFF_EG;
    float* EgWe  = S + OFF_EGWE;
    float* g     = S + OFF_G;
    float* agg   = S + OFF_AGG;
    float* pairE = S + OFF_PAIRE;
    float* eQ    = S + OFF_EQ;
    float* ci    = S + OFF_CI;
    float* hid   = S + OFF_HID;
    float* Wncat = S + OFF_WNCAT;
    float* Wcat  = S + OFF_WCAT;
    float* bcat  = S + OFF_BCAT;

    // L1: all gathers + weight packing
    k_prep<<<PREP_TOTAL, 128>>>(nf, nobj, Xm, ef, eidx, nedg, Eg, opair, pairE,
                                Wn, Wn2, Wncat, lrW1, scrW1, mrW1,
                                lrb1, scrb1, mrb1, Wcat, bcat);
    // L2: batched pre-GEMMs (X@[Wn|Wn2], Eg@We, relu(pairE@We2))
    k_gemm3<<<224, 256>>>(Xm, Wncat, XWcat, Eg, We, EgWe, pairE, We2, eQ);
    // L3: sparse adjacency products (node graph + line graph)
    k_adj<<<Bc * Nc + Bc * Mc, 128>>>(adj, XWcat, nobj, h, ladj, EgWe, nedg, g);
    // L4: scatter-add aggregation over src
    k_agg<<<Bc * Nc, 128>>>(eidx, g, agg);
    // L5: classifier input
    k_build_ci<<<Bc * Pc, 128>>>(opair, nobj, h, agg, XWcat, eQ, ci);
    // L6: fused heads layer-1 GEMM
    k_gemm_heads<<<(Bc * Pc / 128) * 6, 256>>>(ci, Wcat, bcat, hid);
    // L7: fused output layers
    k_heads_out<<<Bc * Pc, 128>>>(hid, lrW2, lrb2, scrW2, scrb2, mrW2, mrb2, out);
}

// round 10
// speedup vs baseline: 2.9254x; 1.1876x over previous
#include <cuda_runtime.h>
#include <cuda_bf16.h>
#include <cstdint>
#include <cstddef>

// ---------------- problem constants ----------------
constexpr int Bc = 16;
constexpr int Nc = 128;
constexpr int Mc = 1024;
constexpr int DNc = 512;
constexpr int DEc = 256;
constexpr int WNc = 128;
constexpr int WEc = 128;
constexpr int Pc = 512;
constexpr int HIDc = 256;
constexpr int CI = 512;        // 2*(WN+WE)
constexpr int HID3 = 3 * HIDc; // 768

// ---------------- scratch (device global, no allocs) ----------------
constexpr size_t OFF_XM    = 0;
constexpr size_t OFF_XWCAT = OFF_XM    + (size_t)Bc*Nc*DNc;    // 2048x256
constexpr size_t OFF_H     = OFF_XWCAT + (size_t)Bc*Nc*256;
constexpr size_t OFF_EG    = OFF_H     + (size_t)Bc*Nc*WNc;
constexpr size_t OFF_EGWE  = OFF_EG    + (size_t)Bc*Mc*DEc;
constexpr size_t OFF_G     = OFF_EGWE  + (size_t)Bc*Mc*WEc;
constexpr size_t OFF_AGG   = OFF_G     + (size_t)Bc*Mc*WEc;
constexpr size_t OFF_PAIRE = OFF_AGG   + (size_t)Bc*Nc*WEc;
constexpr size_t OFF_EQ    = OFF_PAIRE + (size_t)Bc*Pc*DEc;
constexpr size_t OFF_CI    = OFF_EQ    + (size_t)Bc*Pc*WEc;
constexpr size_t OFF_HID   = OFF_CI    + (size_t)Bc*Pc*CI;
constexpr size_t OFF_WNCAT = OFF_HID   + (size_t)Bc*Pc*HID3;   // 512x256
constexpr size_t OFF_WCAT  = OFF_WNCAT + (size_t)DNc*256;      // 512x768
constexpr size_t OFF_BCAT  = OFF_WCAT  + (size_t)CI*HID3;
constexpr size_t SCRATCH_TOTAL = OFF_BCAT + HID3;

__device__ float d_scratch[SCRATCH_TOTAL];

// CSR for scatter-add: per-batch src-node -> ascending edge list
__device__ int d_csr_off[Bc][Nc + 1];
__device__ int d_csr_list[Bc][Mc];

// ---------------- tf32 / cp.async helpers ----------------
__device__ __forceinline__ uint32_t f2tf32(float f) {
    uint32_t u;
    asm("cvt.rna.tf32.f32 %0, %1;" : "=r"(u) : "f"(f));
    return u;
}
__device__ __forceinline__ void mma_tf32(float c[4], const uint32_t a[4], const uint32_t b[2]) {
    asm volatile(
        "mma.sync.aligned.m16n8k8.row.col.f32.tf32.tf32.f32 "
        "{%0,%1,%2,%3}, {%4,%5,%6,%7}, {%8,%9}, {%0,%1,%2,%3};"
        : "+f"(c[0]), "+f"(c[1]), "+f"(c[2]), "+f"(c[3])
        : "r"(a[0]), "r"(a[1]), "r"(a[2]), "r"(a[3]), "r"(b[0]), "r"(b[1]));
}
__device__ __forceinline__ void cp16(void* s, const void* g) {
    uint32_t sa = (uint32_t)__cvta_generic_to_shared(s);
    asm volatile("cp.async.cg.shared.global [%0], [%1], 16;" :: "r"(sa), "l"(g));
}

// ---------------- pipelined tf32 GEMM device function ----------------
constexpr int AS_STR = 20;   // 16 + 4 pad
constexpr int BS_STR = 136;  // 128 + 8 pad

struct SmemGemm {
    float As[2][128][AS_STR];
    float Bs[2][16][BS_STR];
};  // 37,888 bytes

template<int EPI>  // 0 none, 1 relu, 3 bias+relu
__device__ __forceinline__ void gemm_dev(SmemGemm& S,
    const float* __restrict__ A, const float* __restrict__ W, float* __restrict__ C,
    int K, int Ncols, int rowBlk, int colBlk, const float* __restrict__ bias)
{
    const int tid  = threadIdx.x;
    const int wid  = tid >> 5, lane = tid & 31;
    const int wr   = wid >> 1, wc = wid & 1;
    const int g    = lane >> 2, tig = lane & 3;
    const int wrBase = wr * 32, wcBase = wc * 64;

    const int a_row = tid >> 2;
    const int a_c4  = (tid & 3) * 4;
    const int b_row = tid >> 5;
    const int b_c4  = (tid & 31) * 4;

    float acc[2][8][4];
    #pragma unroll
    for (int mt = 0; mt < 2; mt++)
        #pragma unroll
        for (int nt = 0; nt < 8; nt++)
            #pragma unroll
            for (int q = 0; q < 4; q++) acc[mt][nt][q] = 0.f;

    const int KT = K >> 4;

    {
        cp16(&S.As[0][a_row][a_c4],      A + (size_t)(rowBlk + a_row) * K + a_c4);
        cp16(&S.As[0][a_row + 64][a_c4], A + (size_t)(rowBlk + a_row + 64) * K + a_c4);
        cp16(&S.Bs[0][b_row][b_c4],      W + (size_t)b_row * Ncols + colBlk + b_c4);
        cp16(&S.Bs[0][b_row + 8][b_c4],  W + (size_t)(b_row + 8) * Ncols + colBlk + b_c4);
        asm volatile("cp.async.commit_group;");
    }

    for (int kt = 0; kt < KT; kt++) {
        const int cur = kt & 1;
        if (kt + 1 < KT) {
            const int nxt = cur ^ 1;
            const int k0 = (kt + 1) << 4;
            cp16(&S.As[nxt][a_row][a_c4],      A + (size_t)(rowBlk + a_row) * K + k0 + a_c4);
            cp16(&S.As[nxt][a_row + 64][a_c4], A + (size_t)(rowBlk + a_row + 64) * K + k0 + a_c4);
            cp16(&S.Bs[nxt][b_row][b_c4],      W + (size_t)(k0 + b_row) * Ncols + colBlk + b_c4);
            cp16(&S.Bs[nxt][b_row + 8][b_c4],  W + (size_t)(k0 + b_row + 8) * Ncols + colBlk + b_c4);
            asm volatile("cp.async.commit_group;");
            asm volatile("cp.async.wait_group 1;");
        } else {
            asm volatile("cp.async.wait_group 0;");
        }
        __syncthreads();

        #pragma unroll
        for (int ks = 0; ks < 2; ks++) {
            const int kb = ks * 8;
            uint32_t afr[2][4];
            #pragma unroll
            for (int mt = 0; mt < 2; mt++) {
                int rb = wrBase + mt * 16;
                afr[mt][0] = f2tf32(S.As[cur][rb + g    ][kb + tig]);
                afr[mt][1] = f2tf32(S.As[cur][rb + g + 8][kb + tig]);
                afr[mt][2] = f2tf32(S.As[cur][rb + g    ][kb + tig + 4]);
                afr[mt][3] = f2tf32(S.As[cur][rb + g + 8][kb + tig + 4]);
            }
            #pragma unroll
            for (int nt = 0; nt < 8; nt++) {
                uint32_t bfr[2];
                int col = wcBase + nt * 8 + g;
                bfr[0] = f2tf32(S.Bs[cur][kb + tig    ][col]);
                bfr[1] = f2tf32(S.Bs[cur][kb + tig + 4][col]);
                mma_tf32(acc[0][nt], afr[0], bfr);
                mma_tf32(acc[1][nt], afr[1], bfr);
            }
        }
        __syncthreads();
    }

    #pragma unroll
    for (int mt = 0; mt < 2; mt++) {
        int r0 = rowBlk + wrBase + mt * 16 + g;
        int r1 = r0 + 8;
        #pragma unroll
        for (int nt = 0; nt < 8; nt++) {
            int c0 = colBlk + wcBase + nt * 8 + tig * 2;
            float v0 = acc[mt][nt][0], v1 = acc[mt][nt][1];
            float v2 = acc[mt][nt][2], v3 = acc[mt][nt][3];
            if (EPI == 3) {
                float b0 = bias[c0], b1 = bias[c0 + 1];
                v0 += b0; v1 += b1; v2 += b0; v3 += b1;
            }
            if (EPI == 1 || EPI == 3) {
                v0 = fmaxf(v0, 0.f); v1 = fmaxf(v1, 0.f);
                v2 = fmaxf(v2, 0.f); v3 = fmaxf(v3, 0.f);
            }
            *(float2*)(C + (size_t)r0 * Ncols + c0) = make_float2(v0, v1);
            *(float2*)(C + (size_t)r1 * Ncols + c0) = make_float2(v2, v3);
        }
    }
}

// ---------------- L2: batched pre-GEMMs ----------------
__global__ void __launch_bounds__(256) k_gemm3(
    const float* __restrict__ Xm, const float* __restrict__ Wncat, float* __restrict__ XWcat,
    const float* __restrict__ Eg, const float* __restrict__ We, float* __restrict__ EgWe,
    const float* __restrict__ pairE, const float* __restrict__ We2, float* __restrict__ eQ)
{
    __shared__ SmemGemm S;
    int id = blockIdx.x;
    if (id < 32) {
        gemm_dev<0>(S, Xm, Wncat, XWcat, 512, 256, (id >> 1) * 128, (id & 1) * 128, nullptr);
    } else if (id < 160) {
        gemm_dev<0>(S, Eg, We, EgWe, 256, 128, (id - 32) * 128, 0, nullptr);
    } else {
        gemm_dev<1>(S, pairE, We2, eQ, 256, 128, (id - 160) * 128, 0, nullptr);
    }
}

// ---------------- L6: heads GEMM ----------------
__global__ void __launch_bounds__(256) k_gemm_heads(
    const float* __restrict__ ci, const float* __restrict__ Wcat,
    const float* __restrict__ bcat, float* __restrict__ hid)
{
    __shared__ SmemGemm S;
    int id = blockIdx.x;
    gemm_dev<3>(S, ci, Wcat, hid, 512, 768, (id / 6) * 128, (id % 6) * 128, bcat);
}

// ---------------- L1: fused prep (gathers + weight packing + CSR build) ----------------
constexpr int PREP_MASK_END = Bc * Nc;                            // 2048
constexpr int PREP_EG_END   = PREP_MASK_END + Bc * Mc;            // 18432
constexpr int PREP_PAIR_END = PREP_EG_END + Bc * Pc;              // 26624
constexpr int PREP_PW_END   = PREP_PAIR_END + (DNc * WNc) / 128;  // +512
constexpr int PREP_WC_END   = PREP_PW_END + (CI * HIDc) / 128;    // +1024
constexpr int PREP_TOTAL    = PREP_WC_END + Bc;                   // +16 (CSR)

__global__ void __launch_bounds__(128) k_prep(
    const float* __restrict__ nf, const int* __restrict__ nobj, float* __restrict__ Xm,
    const float* __restrict__ ef, const int* __restrict__ eidx, const int* __restrict__ nedg,
    float* __restrict__ Eg, const int* __restrict__ opair, float* __restrict__ pairE,
    const float* __restrict__ Wn, const float* __restrict__ Wn2, float* __restrict__ Wncat,
    const float* __restrict__ lrW1, const float* __restrict__ scrW1, const float* __restrict__ mrW1,
    const float* __restrict__ lrb1, const float* __restrict__ scrb1, const float* __restrict__ mrb1,
    float* __restrict__ Wcat, float* __restrict__ bcat)
{
    const int blk = blockIdx.x, tid = threadIdx.x;
    if (blk < PREP_MASK_END) {
        int b = blk >> 7, n = blk & 127;
        float4 v = make_float4(0.f, 0.f, 0.f, 0.f);
        if (n < nobj[b]) v = ((const float4*)(nf + (size_t)blk * DNc))[tid];
        ((float4*)(Xm + (size_t)blk * DNc))[tid] = v;
    } else if (blk < PREP_EG_END) {
        int bm = blk - PREP_MASK_END;
        int b = bm >> 10, m = bm & 1023;
        float2 v = make_float2(0.f, 0.f);
        if (m < nedg[b]) {
            int s = eidx[b * 2 * Mc + m];
            int d = eidx[b * 2 * Mc + Mc + m];
            v = ((const float2*)(ef + (((size_t)b * Nc + s) * Nc + d) * DEc))[tid];
        }
        ((float2*)(Eg + (size_t)bm * DEc))[tid] = v;
    } else if (blk < PREP_PAIR_END) {
        int bk = blk - PREP_EG_END;
        int b = bk >> 9, k = bk & 511;
        int p0 = opair[(b * Pc + k) * 2 + 0];
        int p1 = opair[(b * Pc + k) * 2 + 1];
        ((float2*)(pairE + (size_t)bk * DEc))[tid] =
            ((const float2*)(ef + (((size_t)b * Nc + p0) * Nc + p1) * DEc))[tid];
    } else if (blk < PREP_PW_END) {
        int idx = (blk - PREP_PAIR_END) * 128 + tid;
        int k = idx >> 7, c = idx & 127;
        Wncat[(size_t)k * 256 + c]       = Wn[idx];
        Wncat[(size_t)k * 256 + 128 + c] = Wn2[idx];
    } else if (blk < PREP_WC_END) {
        int idx = (blk - PREP_PW_END) * 128 + tid;
        int k = idx >> 8, c = idx & 255;
        Wcat[(size_t)k * HID3 + c]             = lrW1[idx];
        Wcat[(size_t)k * HID3 + HIDc + c]      = scrW1[idx];
        Wcat[(size_t)k * HID3 + 2 * HIDc + c]  = mrW1[idx];
        if (blk == PREP_PW_END) {
            for (int i = tid; i < HIDc; i += 128) {
                bcat[i]             = lrb1[i];
                bcat[HIDc + i]      = scrb1[i];
                bcat[2 * HIDc + i]  = mrb1[i];
            }
        }
    } else {
        // CSR build: one block per batch; thread t owns node t (stable, ascending m)
        __shared__ int ssrc[Mc];
        __shared__ int scnt[128];
        int b = blk - PREP_WC_END;
        for (int i = tid; i < Mc; i += 128) ssrc[i] = eidx[b * 2 * Mc + i];
        __syncthreads();
        int cnt = 0;
        for (int m = 0; m < Mc; m++) if (ssrc[m] == tid) cnt++;
        scnt[tid] = cnt;
        __syncthreads();
        int off = 0;
        for (int u = 0; u < tid; u++) off += scnt[u];
        d_csr_off[b][tid] = off;
        if (tid == 127) d_csr_off[b][128] = off + cnt;
        int c = off;
        for (int m = 0; m < Mc; m++)
            if (ssrc[m] == tid) d_csr_list[b][c++] = m;
    }
}

// ---------------- L3: fused sparse adjacency (node + line graph) ----------------
__device__ __forceinline__ void adj_dev(
    const float* __restrict__ Adj, const float* __restrict__ Feat,
    const int* __restrict__ cntArr, float* __restrict__ Out,
    int blk, int ROWLEN, int featStride,
    float* srow, int* sidx, float* sval, int* scount)
{
    const int b   = blk / ROWLEN;
    const int i   = blk % ROWLEN;
    const int tid = threadIdx.x;
    const int cnt = cntArr[b];

    float* outRow = Out + (size_t)blk * 128;
    if (i >= cnt) { outRow[tid] = 0.f; return; }

    // vectorized row stage (float4)
    const float4* A4 = (const float4*)(Adj + ((size_t)b * ROWLEN + i) * ROWLEN);
    float4* s4 = (float4*)srow;
    for (int j = tid; j < (ROWLEN >> 2); j += 128) s4[j] = A4[j];
    __syncthreads();

    if (tid < 32) {
        int cn = 0;
        for (int base = 0; base < ROWLEN; base += 32) {
            int j = base + tid;
            float v = srow[j];
            bool nz = (v != 0.f) && (j < cnt);
            unsigned msk = __ballot_sync(0xffffffffu, nz);
            int pos = cn + __popc(msk & ((1u << tid) - 1u));
            if (nz) { sidx[pos] = j; sval[pos] = v; }
            cn += __popc(msk);
        }
        if (tid == 0) *scount = cn;
    }
    __syncthreads();

    const int n = *scount;
    const float* Fb = Feat + (size_t)b * ROWLEN * featStride;
    float acc = Fb[(size_t)i * featStride + tid];     // + eye*mask term
    for (int t = 0; t < n; t++)
        acc = fmaf(sval[t], Fb[(size_t)sidx[t] * featStride + tid], acc);
    outRow[tid] = fmaxf(acc, 0.f);
}

__global__ void __launch_bounds__(128) k_adj(
    const float* __restrict__ adjN, const float* __restrict__ XWcat,
    const int* __restrict__ nobj, float* __restrict__ h,
    const float* __restrict__ adjM, const float* __restrict__ EgWe,
    const int* __restrict__ nedg, float* __restrict__ g)
{
    __shared__ float srow[Mc];
    __shared__ int   sidx[Mc];
    __shared__ float sval[Mc];
    __shared__ int   scount;
    int blk = blockIdx.x;
    if (blk < Bc * Nc)
        adj_dev(adjN, XWcat, nobj, h, blk, Nc, 256, srow, sidx, sval, &scount);
    else
        adj_dev(adjM, EgWe, nedg, g, blk - Bc * Nc, Mc, 128, srow, sidx, sval, &scount);
}

// ---------------- L4: CSR scatter-add agg ----------------
__global__ void __launch_bounds__(128) k_agg(
    const float* __restrict__ g, float* __restrict__ agg)
{
    int bn = blockIdx.x;
    int b = bn >> 7, n = bn & 127;
    int off = d_csr_off[b][n];
    int end = d_csr_off[b][n + 1];
    const float* gb = g + (size_t)b * Mc * WEc;
    float acc = 0.f;
    for (int t = off; t < end; t++) {
        int m = d_csr_list[b][t];
        acc += gb[(size_t)m * WEc + threadIdx.x];
    }
    agg[(size_t)bn * WEc + threadIdx.x] = acc;
}

// ---------------- L5: build classifier input ----------------
__global__ void __launch_bounds__(128) k_build_ci(
    const int* __restrict__ opair, const int* __restrict__ nobj,
    const float* __restrict__ h, const float* __restrict__ agg,
    const float* __restrict__ XWcat, const float* __restrict__ eQ,
    float* __restrict__ ci)
{
    int bk = blockIdx.x;
    int b = bk >> 9, k = bk & 511;
    int p0 = opair[(b * Pc + k) * 2 + 0];
    int p1 = opair[(b * Pc + k) * 2 + 1];
    int no = nobj[b];
    float nm0 = (p0 < no) ? 1.f : 0.f;
    float nm1 = (p1 < no) ? 1.f : 0.f;
    int c = threadIdx.x;
    const float* hb = h    + (size_t)b * Nc * WNc;
    const float* ab = agg  + (size_t)b * Nc * WEc;
    const float* xb = XWcat + (size_t)b * Nc * 256 + 128;   // Xp = cols [128,256)
    float* co = ci + (size_t)bk * CI;
    co[c]       = hb[(size_t)p0 * WNc + c] + hb[(size_t)p1 * WNc + c];
    co[128 + c] = ab[(size_t)p0 * WEc + c] * nm0 + ab[(size_t)p1 * WEc + c] * nm1;
    co[256 + c] = fmaxf(xb[(size_t)p0 * 256 + c] + xb[(size_t)p1 * 256 + c], 0.f);
    co[384 + c] = eQ[(size_t)bk * WEc + c];
}

// ---------------- L7: fused output layers (lr 9 | cr 6 | mr 17) ----------------
__global__ void __launch_bounds__(128) k_heads_out(
    const float* __restrict__ hid,
    const float* __restrict__ lrW2,  const float* __restrict__ lrb2,
    const float* __restrict__ scrW2, const float* __restrict__ scrb2,
    const float* __restrict__ mrW2,  const float* __restrict__ mrb2,
    float* __restrict__ out)
{
    __shared__ float sh[HID3];
    const int row = blockIdx.x, tid = threadIdx.x;
    const float* hr = hid + (size_t)row * HID3;
    for (int i = tid; i < HID3; i += 128) sh[i] = hr[i];
    __syncthreads();

    const int o    = tid >> 2;   // 0..31
    const int part = tid & 3;
    const float* W2; const float* b2; int off, OUT, oo; float* dst;
    const size_t rows = (size_t)Bc * Pc;
    if (o < 9)       { W2 = lrW2;  b2 = lrb2;  off = 0;   OUT = 9;  oo = o;      dst = out; }
    else if (o < 15) { W2 = scrW2; b2 = scrb2; off = 256; OUT = 6;  oo = o - 9;  dst = out + rows * 9; }
    else             { W2 = mrW2;  b2 = mrb2;  off = 512; OUT = 17; oo = o - 15; dst = out + rows * 15; }

    float acc = 0.f;
    const int k0 = part * 64;
    #pragma unroll 4
    for (int kk = k0; kk < k0 + 64; kk++)
        acc += sh[off + kk] * W2[kk * OUT + oo];
    acc += __shfl_xor_sync(0xffffffffu, acc, 1);
    acc += __shfl_xor_sync(0xffffffffu, acc, 2);
    if (part == 0) dst[(size_t)row * OUT + oo] = acc + b2[oo];
}

// ---------------- launch ----------------
extern "C" void kernel_launch(void* const* d_in, const int* in_sizes, int n_in,
                              void* d_out, int out_size)
{
    const float* nf    = (const float*)d_in[0];
    const float* ef    = (const float*)d_in[1];
    const float* adj   = (const float*)d_in[2];
    const float* ladj  = (const float*)d_in[3];
    const int*   eidx  = (const int*)d_in[4];
    const int*   opair = (const int*)d_in[5];
    const int*   nobj  = (const int*)d_in[6];
    const int*   nedg  = (const int*)d_in[7];
    const float* Wn    = (const float*)d_in[8];
    const float* We    = (const float*)d_in[9];
    const float* Wn2   = (const float*)d_in[10];
    const float* We2   = (const float*)d_in[11];
    const float* scrW1 = (const float*)d_in[12];
    const float* scrb1 = (const float*)d_in[13];
    const float* scrW2 = (const float*)d_in[14];
    const float* scrb2 = (const float*)d_in[15];
    const float* lrW1  = (const float*)d_in[16];
    const float* lrb1  = (const float*)d_in[17];
    const float* lrW2  = (const float*)d_in[18];
    const float* lrb2  = (const float*)d_in[19];
    const float* mrW1  = (const float*)d_in[20];
    const float* mrb1  = (const float*)d_in[21];
    const float* mrW2  = (const float*)d_in[22];
    const float* mrb2  = (const float*)d_in[23];
    float* out = (float*)d_out;

    float* S = nullptr;
    cudaGetSymbolAddress((void**)&S, d_scratch);
    float* Xm    = S + OFF_XM;
    float* XWcat = S + OFF_XWCAT;
    float* h     = S + OFF_H;
    float* Eg    = S + OFF_EG;
    float* EgWe  = S + OFF_EGWE;
    float* g     = S + OFF_G;
    float* agg   = S + OFF_AGG;
    float* pairE = S + OFF_PAIRE;
    float* eQ    = S + OFF_EQ;
    float* ci    = S + OFF_CI;
    float* hid   = S + OFF_HID;
    float* Wncat = S + OFF_WNCAT;
    float* Wcat  = S + OFF_WCAT;
    float* bcat  = S + OFF_BCAT;

    // L1: all gathers + weight packing + CSR build
    k_prep<<<PREP_TOTAL, 128>>>(nf, nobj, Xm, ef, eidx, nedg, Eg, opair, pairE,
                                Wn, Wn2, Wncat, lrW1, scrW1, mrW1,
                                lrb1, scrb1, mrb1, Wcat, bcat);
    // L2: batched pre-GEMMs (X@[Wn|Wn2], Eg@We, relu(pairE@We2))
    k_gemm3<<<224, 256>>>(Xm, Wncat, XWcat, Eg, We, EgWe, pairE, We2, eQ);
    // L3: sparse adjacency products (node graph + line graph)
    k_adj<<<Bc * Nc + Bc * Mc, 128>>>(adj, XWcat, nobj, h, ladj, EgWe, nedg, g);
    // L4: CSR scatter-add aggregation
    k_agg<<<Bc * Nc, 128>>>(g, agg);
    // L5: classifier input
    k_build_ci<<<Bc * Pc, 128>>>(opair, nobj, h, agg, XWcat, eQ, ci);
    // L6: fused heads layer-1 GEMM
    k_gemm_heads<<<(Bc * Pc / 128) * 6, 256>>>(ci, Wcat, bcat, hid);
    // L7: fused output layers
    k_heads_out<<<Bc * Pc, 128>>>(hid, lrW2, lrb2, scrW2, scrb2, mrW2, mrb2, out);
}

// round 11
// speedup vs baseline: 2.9900x; 1.0221x over previous
#include <cuda_runtime.h>
#include <cuda_bf16.h>
#include <cstdint>
#include <cstddef>

// ---------------- problem constants ----------------
constexpr int Bc = 16;
constexpr int Nc = 128;
constexpr int Mc = 1024;
constexpr int DNc = 512;
constexpr int DEc = 256;
constexpr int WNc = 128;
constexpr int WEc = 128;
constexpr int Pc = 512;
constexpr int HIDc = 256;
constexpr int CI = 512;        // 2*(WN+WE)
constexpr int HID3 = 3 * HIDc; // 768

// ---------------- scratch (device global, no allocs) ----------------
constexpr size_t OFF_XM    = 0;
constexpr size_t OFF_XWCAT = OFF_XM    + (size_t)Bc*Nc*DNc;
constexpr size_t OFF_H     = OFF_XWCAT + (size_t)Bc*Nc*256;
constexpr size_t OFF_EG    = OFF_H     + (size_t)Bc*Nc*WNc;
constexpr size_t OFF_EGWE  = OFF_EG    + (size_t)Bc*Mc*DEc;
constexpr size_t OFF_G     = OFF_EGWE  + (size_t)Bc*Mc*WEc;
constexpr size_t OFF_AGG   = OFF_G     + (size_t)Bc*Mc*WEc;
constexpr size_t OFF_PAIRE = OFF_AGG   + (size_t)Bc*Nc*WEc;
constexpr size_t OFF_CI    = OFF_PAIRE + (size_t)Bc*Pc*DEc;
constexpr size_t OFF_HID   = OFF_CI    + (size_t)Bc*Pc*CI;
constexpr size_t OFF_WNCAT = OFF_HID   + (size_t)Bc*Pc*HID3;   // 512x256
constexpr size_t OFF_WCAT  = OFF_WNCAT + (size_t)DNc*256;      // 512x768
constexpr size_t OFF_BCAT  = OFF_WCAT  + (size_t)CI*HID3;      // 768
constexpr size_t OFF_WER   = OFF_BCAT  + HID3;                 // 256x128
constexpr size_t OFF_WE2R  = OFF_WER   + (size_t)DEc*WEc;      // 256x128
constexpr size_t SCRATCH_TOTAL = OFF_WE2R + (size_t)DEc*WEc;

__device__ float d_scratch[SCRATCH_TOTAL];

// CSR for scatter-add: per-batch src-node -> ascending edge list
__device__ int d_csr_off[Bc][Nc + 1];
__device__ int d_csr_list[Bc][Mc];

// ---------------- tf32 / cp.async helpers ----------------
__device__ __forceinline__ uint32_t f2tf32(float f) {
    uint32_t u;
    asm("cvt.rna.tf32.f32 %0, %1;" : "=r"(u) : "f"(f));
    return u;
}
__device__ __forceinline__ float rtf(float f) {      // round-to-tf32, as float bits
    return __uint_as_float(f2tf32(f));
}
__device__ __forceinline__ void mma_tf32(float c[4], const uint32_t a[4], const uint32_t b[2]) {
    asm volatile(
        "mma.sync.aligned.m16n8k8.row.col.f32.tf32.tf32.f32 "
        "{%0,%1,%2,%3}, {%4,%5,%6,%7}, {%8,%9}, {%0,%1,%2,%3};"
        : "+f"(c[0]), "+f"(c[1]), "+f"(c[2]), "+f"(c[3])
        : "r"(a[0]), "r"(a[1]), "r"(a[2]), "r"(a[3]), "r"(b[0]), "r"(b[1]));
}
__device__ __forceinline__ void cp16(void* s, const void* g) {
    uint32_t sa = (uint32_t)__cvta_generic_to_shared(s);
    asm volatile("cp.async.cg.shared.global [%0], [%1], 16;" :: "r"(sa), "l"(g));
}

// ---------------- pipelined tf32 GEMM device function ----------------
// Operands A and W MUST already be tf32-rounded (bits fed raw to mma).
constexpr int AS_STR = 20;   // 16 + 4 pad
constexpr int BS_STR = 136;  // 128 + 8 pad

struct SmemGemm {
    float As[2][128][AS_STR];
    float Bs[2][16][BS_STR];
};  // 37,888 bytes

template<int EPI, bool RND>  // EPI: 0 none, 1 relu, 3 bias+relu; RND: tf32-round output
__device__ __forceinline__ void gemm_dev(SmemGemm& S,
    const float* __restrict__ A, const float* __restrict__ W, float* __restrict__ C,
    int K, int Ncols, int ldc, int rowBlk, int colBlk, const float* __restrict__ bias)
{
    const int tid  = threadIdx.x;
    const int wid  = tid >> 5, lane = tid & 31;
    const int wr   = wid >> 1, wc = wid & 1;
    const int g    = lane >> 2, tig = lane & 3;
    const int wrBase = wr * 32, wcBase = wc * 64;

    const int a_row = tid >> 2;
    const int a_c4  = (tid & 3) * 4;
    const int b_row = tid >> 5;
    const int b_c4  = (tid & 31) * 4;

    float acc[2][8][4];
    #pragma unroll
    for (int mt = 0; mt < 2; mt++)
        #pragma unroll
        for (int nt = 0; nt < 8; nt++)
            #pragma unroll
            for (int q = 0; q < 4; q++) acc[mt][nt][q] = 0.f;

    const int KT = K >> 4;

    {
        cp16(&S.As[0][a_row][a_c4],      A + (size_t)(rowBlk + a_row) * K + a_c4);
        cp16(&S.As[0][a_row + 64][a_c4], A + (size_t)(rowBlk + a_row + 64) * K + a_c4);
        cp16(&S.Bs[0][b_row][b_c4],      W + (size_t)b_row * Ncols + colBlk + b_c4);
        cp16(&S.Bs[0][b_row + 8][b_c4],  W + (size_t)(b_row + 8) * Ncols + colBlk + b_c4);
        asm volatile("cp.async.commit_group;");
    }

    for (int kt = 0; kt < KT; kt++) {
        const int cur = kt & 1;
        if (kt + 1 < KT) {
            const int nxt = cur ^ 1;
            const int k0 = (kt + 1) << 4;
            cp16(&S.As[nxt][a_row][a_c4],      A + (size_t)(rowBlk + a_row) * K + k0 + a_c4);
            cp16(&S.As[nxt][a_row + 64][a_c4], A + (size_t)(rowBlk + a_row + 64) * K + k0 + a_c4);
            cp16(&S.Bs[nxt][b_row][b_c4],      W + (size_t)(k0 + b_row) * Ncols + colBlk + b_c4);
            cp16(&S.Bs[nxt][b_row + 8][b_c4],  W + (size_t)(k0 + b_row + 8) * Ncols + colBlk + b_c4);
            asm volatile("cp.async.commit_group;");
            asm volatile("cp.async.wait_group 1;");
        } else {
            asm volatile("cp.async.wait_group 0;");
        }
        __syncthreads();

        #pragma unroll
        for (int ks = 0; ks < 2; ks++) {
            const int kb = ks * 8;
            uint32_t afr[2][4];
            #pragma unroll
            for (int mt = 0; mt < 2; mt++) {
                int rb = wrBase + mt * 16;
                afr[mt][0] = __float_as_uint(S.As[cur][rb + g    ][kb + tig]);
                afr[mt][1] = __float_as_uint(S.As[cur][rb + g + 8][kb + tig]);
                afr[mt][2] = __float_as_uint(S.As[cur][rb + g    ][kb + tig + 4]);
                afr[mt][3] = __float_as_uint(S.As[cur][rb + g + 8][kb + tig + 4]);
            }
            #pragma unroll
            for (int nt = 0; nt < 8; nt++) {
                uint32_t bfr[2];
                int col = wcBase + nt * 8 + g;
                bfr[0] = __float_as_uint(S.Bs[cur][kb + tig    ][col]);
                bfr[1] = __float_as_uint(S.Bs[cur][kb + tig + 4][col]);
                mma_tf32(acc[0][nt], afr[0], bfr);
                mma_tf32(acc[1][nt], afr[1], bfr);
            }
        }
        __syncthreads();
    }

    #pragma unroll
    for (int mt = 0; mt < 2; mt++) {
        int r0 = rowBlk + wrBase + mt * 16 + g;
        int r1 = r0 + 8;
        #pragma unroll
        for (int nt = 0; nt < 8; nt++) {
            int c0 = colBlk + wcBase + nt * 8 + tig * 2;
            float v0 = acc[mt][nt][0], v1 = acc[mt][nt][1];
            float v2 = acc[mt][nt][2], v3 = acc[mt][nt][3];
            if (EPI == 3) {
                float b0 = bias[c0], b1 = bias[c0 + 1];
                v0 += b0; v1 += b1; v2 += b0; v3 += b1;
            }
            if (EPI == 1 || EPI == 3) {
                v0 = fmaxf(v0, 0.f); v1 = fmaxf(v1, 0.f);
                v2 = fmaxf(v2, 0.f); v3 = fmaxf(v3, 0.f);
            }
            if (RND) { v0 = rtf(v0); v1 = rtf(v1); v2 = rtf(v2); v3 = rtf(v3); }
            *(float2*)(C + (size_t)r0 * ldc + c0) = make_float2(v0, v1);
            *(float2*)(C + (size_t)r1 * ldc + c0) = make_float2(v2, v3);
        }
    }
}

// ---------------- L2: batched pre-GEMMs ----------------
__global__ void __launch_bounds__(256) k_gemm3(
    const float* __restrict__ Xm, const float* __restrict__ Wncat, float* __restrict__ XWcat,
    const float* __restrict__ Eg, const float* __restrict__ WeR, float* __restrict__ EgWe,
    const float* __restrict__ pairE, const float* __restrict__ We2R, float* __restrict__ ci)
{
    __shared__ SmemGemm S;
    int id = blockIdx.x;
    if (id < 32) {
        gemm_dev<0,false>(S, Xm, Wncat, XWcat, 512, 256, 256, (id >> 1) * 128, (id & 1) * 128, nullptr);
    } else if (id < 160) {
        gemm_dev<0,false>(S, Eg, WeR, EgWe, 256, 128, 128, (id - 32) * 128, 0, nullptr);
    } else {
        // relu(pairE @ We2), tf32-rounded, written straight into ci[:, 384:512]
        gemm_dev<1,true>(S, pairE, We2R, ci + 384, 256, 128, CI, (id - 160) * 128, 0, nullptr);
    }
}

// ---------------- L6: heads GEMM ----------------
__global__ void __launch_bounds__(256) k_gemm_heads(
    const float* __restrict__ ci, const float* __restrict__ Wcat,
    const float* __restrict__ bcat, float* __restrict__ hid)
{
    __shared__ SmemGemm S;
    int id = blockIdx.x;
    gemm_dev<3,false>(S, ci, Wcat, hid, 512, 768, 768, (id / 6) * 128, (id % 6) * 128, bcat);
}

// ---------------- L1: fused prep (gathers + weight packing + CSR build) ----------------
constexpr int PREP_MASK_END = Bc * Nc;                            // 2048
constexpr int PREP_EG_END   = PREP_MASK_END + Bc * Mc;            // 18432
constexpr int PREP_PAIR_END = PREP_EG_END + Bc * Pc;              // 26624
constexpr int PREP_PW_END   = PREP_PAIR_END + (DNc * WNc) / 128;  // +512
constexpr int PREP_WC_END   = PREP_PW_END + (CI * HIDc) / 128;    // +1024
constexpr int PREP_WE_END   = PREP_WC_END + (DEc * WEc) / 512;    // +64 (float4 x128thr)
constexpr int PREP_WE2_END  = PREP_WE_END + (DEc * WEc) / 512;    // +64
constexpr int PREP_TOTAL    = PREP_WE2_END + Bc;                  // +16 (CSR)

__global__ void __launch_bounds__(128) k_prep(
    const float* __restrict__ nf, const int* __restrict__ nobj, float* __restrict__ Xm,
    const float* __restrict__ ef, const int* __restrict__ eidx, const int* __restrict__ nedg,
    float* __restrict__ Eg, const int* __restrict__ opair, float* __restrict__ pairE,
    const float* __restrict__ Wn, const float* __restrict__ Wn2, float* __restrict__ Wncat,
    const float* __restrict__ lrW1, const float* __restrict__ scrW1, const float* __restrict__ mrW1,
    const float* __restrict__ lrb1, const float* __restrict__ scrb1, const float* __restrict__ mrb1,
    float* __restrict__ Wcat, float* __restrict__ bcat,
    const float* __restrict__ We, const float* __restrict__ We2,
    float* __restrict__ WeR, float* __restrict__ We2R)
{
    const int blk = blockIdx.x, tid = threadIdx.x;
    if (blk < PREP_MASK_END) {
        int b = blk >> 7, n = blk & 127;
        float4 v = make_float4(0.f, 0.f, 0.f, 0.f);
        if (n < nobj[b]) {
            v = ((const float4*)(nf + (size_t)blk * DNc))[tid];
            v.x = rtf(v.x); v.y = rtf(v.y); v.z = rtf(v.z); v.w = rtf(v.w);
        }
        ((float4*)(Xm + (size_t)blk * DNc))[tid] = v;
    } else if (blk < PREP_EG_END) {
        int bm = blk - PREP_MASK_END;
        int b = bm >> 10, m = bm & 1023;
        float2 v = make_float2(0.f, 0.f);
        if (m < nedg[b]) {
            int s = eidx[b * 2 * Mc + m];
            int d = eidx[b * 2 * Mc + Mc + m];
            v = ((const float2*)(ef + (((size_t)b * Nc + s) * Nc + d) * DEc))[tid];
            v.x = rtf(v.x); v.y = rtf(v.y);
        }
        ((float2*)(Eg + (size_t)bm * DEc))[tid] = v;
    } else if (blk < PREP_PAIR_END) {
        int bk = blk - PREP_EG_END;
        int b = bk >> 9, k = bk & 511;
        int p0 = opair[(b * Pc + k) * 2 + 0];
        int p1 = opair[(b * Pc + k) * 2 + 1];
        float2 v = ((const float2*)(ef + (((size_t)b * Nc + p0) * Nc + p1) * DEc))[tid];
        v.x = rtf(v.x); v.y = rtf(v.y);
        ((float2*)(pairE + (size_t)bk * DEc))[tid] = v;
    } else if (blk < PREP_PW_END) {
        int idx = (blk - PREP_PAIR_END) * 128 + tid;
        int k = idx >> 7, c = idx & 127;
        Wncat[(size_t)k * 256 + c]       = rtf(Wn[idx]);
        Wncat[(size_t)k * 256 + 128 + c] = rtf(Wn2[idx]);
    } else if (blk < PREP_WC_END) {
        int idx = (blk - PREP_PW_END) * 128 + tid;
        int k = idx >> 8, c = idx & 255;
        Wcat[(size_t)k * HID3 + c]             = rtf(lrW1[idx]);
        Wcat[(size_t)k * HID3 + HIDc + c]      = rtf(scrW1[idx]);
        Wcat[(size_t)k * HID3 + 2 * HIDc + c]  = rtf(mrW1[idx]);
        if (blk == PREP_PW_END) {
            for (int i = tid; i < HIDc; i += 128) {
                bcat[i]             = lrb1[i];
                bcat[HIDc + i]      = scrb1[i];
                bcat[2 * HIDc + i]  = mrb1[i];
            }
        }
    } else if (blk < PREP_WE_END) {
        int idx = (blk - PREP_WC_END) * 128 + tid;     // float4 index
        float4 v = ((const float4*)We)[idx];
        v.x = rtf(v.x); v.y = rtf(v.y); v.z = rtf(v.z); v.w = rtf(v.w);
        ((float4*)WeR)[idx] = v;
    } else if (blk < PREP_WE2_END) {
        int idx = (blk - PREP_WE_END) * 128 + tid;
        float4 v = ((const float4*)We2)[idx];
        v.x = rtf(v.x); v.y = rtf(v.y); v.z = rtf(v.z); v.w = rtf(v.w);
        ((float4*)We2R)[idx] = v;
    } else {
        // CSR build: one block per batch; thread t owns node t (stable, ascending m)
        __shared__ int ssrc[Mc];
        __shared__ int scnt[128];
        int b = blk - PREP_WE2_END;
        for (int i = tid; i < Mc; i += 128) ssrc[i] = eidx[b * 2 * Mc + i];
        __syncthreads();
        int cnt = 0;
        for (int m = 0; m < Mc; m++) if (ssrc[m] == tid) cnt++;
        scnt[tid] = cnt;
        __syncthreads();
        int off = 0;
        for (int u = 0; u < tid; u++) off += scnt[u];
        d_csr_off[b][tid] = off;
        if (tid == 127) d_csr_off[b][128] = off + cnt;
        int c = off;
        for (int m = 0; m < Mc; m++)
            if (ssrc[m] == tid) d_csr_list[b][c++] = m;
    }
}

// ---------------- L3: fused sparse adjacency (node + line graph) ----------------
__device__ __forceinline__ void adj_dev(
    const float* __restrict__ Adj, const float* __restrict__ Feat,
    const int* __restrict__ cntArr, float* __restrict__ Out,
    int blk, int ROWLEN, int featStride,
    float* srow, int* sidx, float* sval, int* scount)
{
    const int b   = blk / ROWLEN;
    const int i   = blk % ROWLEN;
    const int tid = threadIdx.x;
    const int cnt = cntArr[b];

    float* outRow = Out + (size_t)blk * 128;
    if (i >= cnt) { outRow[tid] = 0.f; return; }

    const float4* A4 = (const float4*)(Adj + ((size_t)b * ROWLEN + i) * ROWLEN);
    float4* s4 = (float4*)srow;
    for (int j = tid; j < (ROWLEN >> 2); j += 128) s4[j] = A4[j];
    __syncthreads();

    if (tid < 32) {
        int cn = 0;
        for (int base = 0; base < ROWLEN; base += 32) {
            int j = base + tid;
            float v = srow[j];
            bool nz = (v != 0.f) && (j < cnt);
            unsigned msk = __ballot_sync(0xffffffffu, nz);
            int pos = cn + __popc(msk & ((1u << tid) - 1u));
            if (nz) { sidx[pos] = j; sval[pos] = v; }
            cn += __popc(msk);
        }
        if (tid == 0) *scount = cn;
    }
    __syncthreads();

    const int n = *scount;
    const float* Fb = Feat + (size_t)b * ROWLEN * featStride;
    float acc = Fb[(size_t)i * featStride + tid];     // + eye*mask term
    for (int t = 0; t < n; t++)
        acc = fmaf(sval[t], Fb[(size_t)sidx[t] * featStride + tid], acc);
    outRow[tid] = fmaxf(acc, 0.f);
}

__global__ void __launch_bounds__(128) k_adj(
    const float* __restrict__ adjN, const float* __restrict__ XWcat,
    const int* __restrict__ nobj, float* __restrict__ h,
    const float* __restrict__ adjM, const float* __restrict__ EgWe,
    const int* __restrict__ nedg, float* __restrict__ g)
{
    __shared__ float srow[Mc];
    __shared__ int   sidx[Mc];
    __shared__ float sval[Mc];
    __shared__ int   scount;
    int blk = blockIdx.x;
    if (blk < Bc * Nc)
        adj_dev(adjN, XWcat, nobj, h, blk, Nc, 256, srow, sidx, sval, &scount);
    else
        adj_dev(adjM, EgWe, nedg, g, blk - Bc * Nc, Mc, 128, srow, sidx, sval, &scount);
}

// ---------------- L4: CSR scatter-add agg ----------------
__global__ void __launch_bounds__(128) k_agg(
    const float* __restrict__ g, float* __restrict__ agg)
{
    int bn = blockIdx.x;
    int b = bn >> 7, n = bn & 127;
    int off = d_csr_off[b][n];
    int end = d_csr_off[b][n + 1];
    const float* gb = g + (size_t)b * Mc * WEc;
    float acc = 0.f;
    for (int t = off; t < end; t++) {
        int m = d_csr_list[b][t];
        acc += gb[(size_t)m * WEc + threadIdx.x];
    }
    agg[(size_t)bn * WEc + threadIdx.x] = acc;
}

// ---------------- L5: build classifier input (cols 0..384; col 384+ done by gemm3) --
__global__ void __launch_bounds__(128) k_build_ci(
    const int* __restrict__ opair, const int* __restrict__ nobj,
    const float* __restrict__ h, const float* __restrict__ agg,
    const float* __restrict__ XWcat, float* __restrict__ ci)
{
    int bk = blockIdx.x;
    int b = bk >> 9, k = bk & 511;
    int p0 = opair[(b * Pc + k) * 2 + 0];
    int p1 = opair[(b * Pc + k) * 2 + 1];
    int no = nobj[b];
    float nm0 = (p0 < no) ? 1.f : 0.f;
    float nm1 = (p1 < no) ? 1.f : 0.f;
    int c = threadIdx.x;
    const float* hb = h    + (size_t)b * Nc * WNc;
    const float* ab = agg  + (size_t)b * Nc * WEc;
    const float* xb = XWcat + (size_t)b * Nc * 256 + 128;   // Xp = cols [128,256)
    float* co = ci + (size_t)bk * CI;
    co[c]       = rtf(hb[(size_t)p0 * WNc + c] + hb[(size_t)p1 * WNc + c]);
    co[128 + c] = rtf(ab[(size_t)p0 * WEc + c] * nm0 + ab[(size_t)p1 * WEc + c] * nm1);
    co[256 + c] = rtf(fmaxf(xb[(size_t)p0 * 256 + c] + xb[(size_t)p1 * 256 + c], 0.f));
}

// ---------------- L7: fused output layers (lr 9 | cr 6 | mr 17) ----------------
__global__ void __launch_bounds__(128) k_heads_out(
    const float* __restrict__ hid,
    const float* __restrict__ lrW2,  const float* __restrict__ lrb2,
    const float* __restrict__ scrW2, const float* __restrict__ scrb2,
    const float* __restrict__ mrW2,  const float* __restrict__ mrb2,
    float* __restrict__ out)
{
    __shared__ float sh[HID3];
    const int row = blockIdx.x, tid = threadIdx.x;
    const float* hr = hid + (size_t)row * HID3;
    for (int i = tid; i < HID3; i += 128) sh[i] = hr[i];
    __syncthreads();

    const int o    = tid >> 2;   // 0..31
    const int part = tid & 3;
    const float* W2; const float* b2; int off, OUT, oo; float* dst;
    const size_t rows = (size_t)Bc * Pc;
    if (o < 9)       { W2 = lrW2;  b2 = lrb2;  off = 0;   OUT = 9;  oo = o;      dst = out; }
    else if (o < 15) { W2 = scrW2; b2 = scrb2; off = 256; OUT = 6;  oo = o - 9;  dst = out + rows * 9; }
    else             { W2 = mrW2;  b2 = mrb2;  off = 512; OUT = 17; oo = o - 15; dst = out + rows * 15; }

    float acc = 0.f;
    const int k0 = part * 64;
    #pragma unroll 4
    for (int kk = k0; kk < k0 + 64; kk++)
        acc += sh[off + kk] * W2[kk * OUT + oo];
    acc += __shfl_xor_sync(0xffffffffu, acc, 1);
    acc += __shfl_xor_sync(0xffffffffu, acc, 2);
    if (part == 0) dst[(size_t)row * OUT + oo] = acc + b2[oo];
}

// ---------------- launch ----------------
extern "C" void kernel_launch(void* const* d_in, const int* in_sizes, int n_in,
                              void* d_out, int out_size)
{
    const float* nf    = (const float*)d_in[0];
    const float* ef    = (const float*)d_in[1];
    const float* adj   = (const float*)d_in[2];
    const float* ladj  = (const float*)d_in[3];
    const int*   eidx  = (const int*)d_in[4];
    const int*   opair = (const int*)d_in[5];
    const int*   nobj  = (const int*)d_in[6];
    const int*   nedg  = (const int*)d_in[7];
    const float* Wn    = (const float*)d_in[8];
    const float* We    = (const float*)d_in[9];
    const float* Wn2   = (const float*)d_in[10];
    const float* We2   = (const float*)d_in[11];
    const float* scrW1 = (const float*)d_in[12];
    const float* scrb1 = (const float*)d_in[13];
    const float* scrW2 = (const float*)d_in[14];
    const float* scrb2 = (const float*)d_in[15];
    const float* lrW1  = (const float*)d_in[16];
    const float* lrb1  = (const float*)d_in[17];
    const float* lrW2  = (const float*)d_in[18];
    const float* lrb2  = (const float*)d_in[19];
    const float* mrW1  = (const float*)d_in[20];
    const float* mrb1  = (const float*)d_in[21];
    const float* mrW2  = (const float*)d_in[22];
    const float* mrb2  = (const float*)d_in[23];
    float* out = (float*)d_out;

    float* S = nullptr;
    cudaGetSymbolAddress((void**)&S, d_scratch);
    float* Xm    = S + OFF_XM;
    float* XWcat = S + OFF_XWCAT;
    float* h     = S + OFF_H;
    float* Eg    = S + OFF_EG;
    float* EgWe  = S + OFF_EGWE;
    float* g     = S + OFF_G;
    float* agg   = S + OFF_AGG;
    float* pairE = S + OFF_PAIRE;
    float* ci    = S + OFF_CI;
    float* hid   = S + OFF_HID;
    float* Wncat = S + OFF_WNCAT;
    float* Wcat  = S + OFF_WCAT;
    float* bcat  = S + OFF_BCAT;
    float* WeR   = S + OFF_WER;
    float* We2R  = S + OFF_WE2R;

    // L1: gathers + tf32 pre-rounding + weight packing + CSR build
    k_prep<<<PREP_TOTAL, 128>>>(nf, nobj, Xm, ef, eidx, nedg, Eg, opair, pairE,
                                Wn, Wn2, Wncat, lrW1, scrW1, mrW1,
                                lrb1, scrb1, mrb1, Wcat, bcat,
                                We, We2, WeR, We2R);
    // L2: batched pre-GEMMs (X@[Wn|Wn2], Eg@We, relu(pairE@We2)->ci[:,384:])
    k_gemm3<<<224, 256>>>(Xm, Wncat, XWcat, Eg, WeR, EgWe, pairE, We2R, ci);
    // L3: sparse adjacency products (node graph + line graph)
    k_adj<<<Bc * Nc + Bc * Mc, 128>>>(adj, XWcat, nobj, h, ladj, EgWe, nedg, g);
    // L4: CSR scatter-add aggregation
    k_agg<<<Bc * Nc, 128>>>(g, agg);
    // L5: classifier input (cols 0..384)
    k_build_ci<<<Bc * Pc, 128>>>(opair, nobj, h, agg, XWcat, ci);
    // L6: fused heads layer-1 GEMM
    k_gemm_heads<<<(Bc * Pc / 128) * 6, 256>>>(ci, Wcat, bcat, hid);
    // L7: fused output layers
    k_heads_out<<<Bc * Pc, 128>>>(hid, lrW2, lrb2, scrW2, scrb2, mrW2, mrb2, out);
}

// round 12
// speedup vs baseline: 3.1136x; 1.0414x over previous
#include <cuda_runtime.h>
#include <cuda_bf16.h>
#include <cstdint>
#include <cstddef>

// ---------------- problem constants ----------------
constexpr int Bc = 16;
constexpr int Nc = 128;
constexpr int Mc = 1024;
constexpr int DNc = 512;
constexpr int DEc = 256;
constexpr int WNc = 128;
constexpr int WEc = 128;
constexpr int Pc = 512;
constexpr int HIDc = 256;
constexpr int CI = 512;        // 2*(WN+WE)
constexpr int HID3 = 3 * HIDc; // 768

// ---------------- scratch (device global, no allocs) ----------------
constexpr size_t OFF_XM    = 0;
constexpr size_t OFF_XWCAT = OFF_XM    + (size_t)Bc*Nc*DNc;
constexpr size_t OFF_H     = OFF_XWCAT + (size_t)Bc*Nc*256;
constexpr size_t OFF_EG    = OFF_H     + (size_t)Bc*Nc*WNc;
constexpr size_t OFF_EGWE  = OFF_EG    + (size_t)Bc*Mc*DEc;
constexpr size_t OFF_G     = OFF_EGWE  + (size_t)Bc*Mc*WEc;
constexpr size_t OFF_AGG   = OFF_G     + (size_t)Bc*Mc*WEc;
constexpr size_t OFF_PAIRE = OFF_AGG   + (size_t)Bc*Nc*WEc;
constexpr size_t OFF_CI    = OFF_PAIRE + (size_t)Bc*Pc*DEc;
constexpr size_t OFF_HID   = OFF_CI    + (size_t)Bc*Pc*CI;
constexpr size_t OFF_WNCAT = OFF_HID   + (size_t)Bc*Pc*HID3;   // 512x256
constexpr size_t OFF_WCAT  = OFF_WNCAT + (size_t)DNc*256;      // 512x768
constexpr size_t OFF_BCAT  = OFF_WCAT  + (size_t)CI*HID3;      // 768
constexpr size_t OFF_WER   = OFF_BCAT  + HID3;                 // 256x128
constexpr size_t OFF_WE2R  = OFF_WER   + (size_t)DEc*WEc;      // 256x128
constexpr size_t SCRATCH_TOTAL = OFF_WE2R + (size_t)DEc*WEc;

__device__ float d_scratch[SCRATCH_TOTAL];

// CSR for scatter-add: per-batch src-node -> ascending edge list
__device__ int d_csr_off[Bc][Nc + 1];
__device__ int d_csr_list[Bc][Mc];

// ---------------- tf32 / cp.async helpers ----------------
__device__ __forceinline__ uint32_t f2tf32(float f) {
    uint32_t u;
    asm("cvt.rna.tf32.f32 %0, %1;" : "=r"(u) : "f"(f));
    return u;
}
__device__ __forceinline__ float rtf(float f) {
    return __uint_as_float(f2tf32(f));
}
__device__ __forceinline__ void mma_tf32(float c[4], const uint32_t a[4], const uint32_t b[2]) {
    asm volatile(
        "mma.sync.aligned.m16n8k8.row.col.f32.tf32.tf32.f32 "
        "{%0,%1,%2,%3}, {%4,%5,%6,%7}, {%8,%9}, {%0,%1,%2,%3};"
        : "+f"(c[0]), "+f"(c[1]), "+f"(c[2]), "+f"(c[3])
        : "r"(a[0]), "r"(a[1]), "r"(a[2]), "r"(a[3]), "r"(b[0]), "r"(b[1]));
}
__device__ __forceinline__ void cp16(void* s, const void* g) {
    uint32_t sa = (uint32_t)__cvta_generic_to_shared(s);
    asm volatile("cp.async.cg.shared.global [%0], [%1], 16;" :: "r"(sa), "l"(g));
}

// ---------------- pipelined tf32 GEMM device function ----------------
// Operands A and W MUST already be tf32-rounded (bits fed raw to mma).
constexpr int AS_STR = 20;
constexpr int BS_STR = 136;

struct SmemGemm {
    float As[2][128][AS_STR];
    float Bs[2][16][BS_STR];
};  // 37,888 bytes

template<int EPI, bool RND>  // EPI: 0 none, 1 relu, 3 bias+relu; RND: tf32-round output
__device__ __forceinline__ void gemm_dev(SmemGemm& S,
    const float* __restrict__ A, const float* __restrict__ W, float* __restrict__ C,
    int K, int Ncols, int ldc, int rowBlk, int colBlk, const float* __restrict__ bias)
{
    const int tid  = threadIdx.x;
    const int wid  = tid >> 5, lane = tid & 31;
    const int wr   = wid >> 1, wc = wid & 1;
    const int g    = lane >> 2, tig = lane & 3;
    const int wrBase = wr * 32, wcBase = wc * 64;

    const int a_row = tid >> 2;
    const int a_c4  = (tid & 3) * 4;
    const int b_row = tid >> 5;
    const int b_c4  = (tid & 31) * 4;

    float acc[2][8][4];
    #pragma unroll
    for (int mt = 0; mt < 2; mt++)
        #pragma unroll
        for (int nt = 0; nt < 8; nt++)
            #pragma unroll
            for (int q = 0; q < 4; q++) acc[mt][nt][q] = 0.f;

    const int KT = K >> 4;

    {
        cp16(&S.As[0][a_row][a_c4],      A + (size_t)(rowBlk + a_row) * K + a_c4);
        cp16(&S.As[0][a_row + 64][a_c4], A + (size_t)(rowBlk + a_row + 64) * K + a_c4);
        cp16(&S.Bs[0][b_row][b_c4],      W + (size_t)b_row * Ncols + colBlk + b_c4);
        cp16(&S.Bs[0][b_row + 8][b_c4],  W + (size_t)(b_row + 8) * Ncols + colBlk + b_c4);
        asm volatile("cp.async.commit_group;");
    }

    for (int kt = 0; kt < KT; kt++) {
        const int cur = kt & 1;
        if (kt + 1 < KT) {
            const int nxt = cur ^ 1;
            const int k0 = (kt + 1) << 4;
            cp16(&S.As[nxt][a_row][a_c4],      A + (size_t)(rowBlk + a_row) * K + k0 + a_c4);
            cp16(&S.As[nxt][a_row + 64][a_c4], A + (size_t)(rowBlk + a_row + 64) * K + k0 + a_c4);
            cp16(&S.Bs[nxt][b_row][b_c4],      W + (size_t)(k0 + b_row) * Ncols + colBlk + b_c4);
            cp16(&S.Bs[nxt][b_row + 8][b_c4],  W + (size_t)(k0 + b_row + 8) * Ncols + colBlk + b_c4);
            asm volatile("cp.async.commit_group;");
            asm volatile("cp.async.wait_group 1;");
        } else {
            asm volatile("cp.async.wait_group 0;");
        }
        __syncthreads();

        #pragma unroll
        for (int ks = 0; ks < 2; ks++) {
            const int kb = ks * 8;
            uint32_t afr[2][4];
            #pragma unroll
            for (int mt = 0; mt < 2; mt++) {
                int rb = wrBase + mt * 16;
                afr[mt][0] = __float_as_uint(S.As[cur][rb + g    ][kb + tig]);
                afr[mt][1] = __float_as_uint(S.As[cur][rb + g + 8][kb + tig]);
                afr[mt][2] = __float_as_uint(S.As[cur][rb + g    ][kb + tig + 4]);
                afr[mt][3] = __float_as_uint(S.As[cur][rb + g + 8][kb + tig + 4]);
            }
            #pragma unroll
            for (int nt = 0; nt < 8; nt++) {
                uint32_t bfr[2];
                int col = wcBase + nt * 8 + g;
                bfr[0] = __float_as_uint(S.Bs[cur][kb + tig    ][col]);
                bfr[1] = __float_as_uint(S.Bs[cur][kb + tig + 4][col]);
                mma_tf32(acc[0][nt], afr[0], bfr);
                mma_tf32(acc[1][nt], afr[1], bfr);
            }
        }
        __syncthreads();
    }

    #pragma unroll
    for (int mt = 0; mt < 2; mt++) {
        int r0 = rowBlk + wrBase + mt * 16 + g;
        int r1 = r0 + 8;
        #pragma unroll
        for (int nt = 0; nt < 8; nt++) {
            int c0 = colBlk + wcBase + nt * 8 + tig * 2;
            float v0 = acc[mt][nt][0], v1 = acc[mt][nt][1];
            float v2 = acc[mt][nt][2], v3 = acc[mt][nt][3];
            if (EPI == 3) {
                float b0 = bias[c0], b1 = bias[c0 + 1];
                v0 += b0; v1 += b1; v2 += b0; v3 += b1;
            }
            if (EPI == 1 || EPI == 3) {
                v0 = fmaxf(v0, 0.f); v1 = fmaxf(v1, 0.f);
                v2 = fmaxf(v2, 0.f); v3 = fmaxf(v3, 0.f);
            }
            if (RND) { v0 = rtf(v0); v1 = rtf(v1); v2 = rtf(v2); v3 = rtf(v3); }
            *(float2*)(C + (size_t)r0 * ldc + c0) = make_float2(v0, v1);
            *(float2*)(C + (size_t)r1 * ldc + c0) = make_float2(v2, v3);
        }
    }
}

// ---------------- branch GEMM kernels ----------------
__global__ void __launch_bounds__(256) k_gemm_node(
    const float* __restrict__ Xm, const float* __restrict__ Wncat, float* __restrict__ XWcat)
{
    __shared__ SmemGemm S;
    int id = blockIdx.x;  // 32
    gemm_dev<0,false>(S, Xm, Wncat, XWcat, 512, 256, 256, (id >> 1) * 128, (id & 1) * 128, nullptr);
}

__global__ void __launch_bounds__(256) k_gemm_edge(
    const float* __restrict__ Eg, const float* __restrict__ WeR, float* __restrict__ EgWe)
{
    __shared__ SmemGemm S;
    gemm_dev<0,false>(S, Eg, WeR, EgWe, 256, 128, 128, blockIdx.x * 128, 0, nullptr);
}

__global__ void __launch_bounds__(256) k_gemm_pair(
    const float* __restrict__ pairE, const float* __restrict__ We2R, float* __restrict__ ci)
{
    __shared__ SmemGemm S;
    // relu(pairE @ We2), tf32-rounded, written straight into ci[:, 384:512]
    gemm_dev<1,true>(S, pairE, We2R, ci + 384, 256, 128, CI, blockIdx.x * 128, 0, nullptr);
}

__global__ void __launch_bounds__(256) k_gemm_heads(
    const float* __restrict__ ci, const float* __restrict__ Wcat,
    const float* __restrict__ bcat, float* __restrict__ hid)
{
    __shared__ SmemGemm S;
    int id = blockIdx.x;  // 384
    gemm_dev<3,false>(S, ci, Wcat, hid, 512, 768, 768, (id / 6) * 128, (id % 6) * 128, bcat);
}

// ---------------- prep kernels (per branch) ----------------
// EDGE branch: Eg gather [0,16384) + WeR [16384,16448) + CSR [16448,16464)
constexpr int PE_EG_END  = Bc * Mc;                    // 16384
constexpr int PE_WE_END  = PE_EG_END + (DEc * WEc) / 512;  // +64
constexpr int PE_TOTAL   = PE_WE_END + Bc;             // +16

__global__ void __launch_bounds__(128) k_prep_edge(
    const float* __restrict__ ef, const int* __restrict__ eidx, const int* __restrict__ nedg,
    float* __restrict__ Eg, const float* __restrict__ We, float* __restrict__ WeR)
{
    const int blk = blockIdx.x, tid = threadIdx.x;
    if (blk < PE_EG_END) {
        int b = blk >> 10, m = blk & 1023;
        float2 v = make_float2(0.f, 0.f);
        if (m < nedg[b]) {
            int s = eidx[b * 2 * Mc + m];
            int d = eidx[b * 2 * Mc + Mc + m];
            v = ((const float2*)(ef + (((size_t)b * Nc + s) * Nc + d) * DEc))[tid];
            v.x = rtf(v.x); v.y = rtf(v.y);
        }
        ((float2*)(Eg + (size_t)blk * DEc))[tid] = v;
    } else if (blk < PE_WE_END) {
        int idx = (blk - PE_EG_END) * 128 + tid;
        float4 v = ((const float4*)We)[idx];
        v.x = rtf(v.x); v.y = rtf(v.y); v.z = rtf(v.z); v.w = rtf(v.w);
        ((float4*)WeR)[idx] = v;
    } else {
        __shared__ int ssrc[Mc];
        __shared__ int scnt[128];
        int b = blk - PE_WE_END;
        for (int i = tid; i < Mc; i += 128) ssrc[i] = eidx[b * 2 * Mc + i];
        __syncthreads();
        int cnt = 0;
        for (int m = 0; m < Mc; m++) if (ssrc[m] == tid) cnt++;
        scnt[tid] = cnt;
        __syncthreads();
        int off = 0;
        for (int u = 0; u < tid; u++) off += scnt[u];
        d_csr_off[b][tid] = off;
        if (tid == 127) d_csr_off[b][128] = off + cnt;
        int c = off;
        for (int m = 0; m < Mc; m++)
            if (ssrc[m] == tid) d_csr_list[b][c++] = m;
    }
}

// NODE branch: Xm [0,2048) + Wncat [2048,2560) + Wcat/bcat [2560,3584)
constexpr int PN_XM_END = Bc * Nc;                       // 2048
constexpr int PN_WN_END = PN_XM_END + (DNc * WNc) / 128; // +512
constexpr int PN_TOTAL  = PN_WN_END + (CI * HIDc) / 128; // +1024

__global__ void __launch_bounds__(128) k_prep_node(
    const float* __restrict__ nf, const int* __restrict__ nobj, float* __restrict__ Xm,
    const float* __restrict__ Wn, const float* __restrict__ Wn2, float* __restrict__ Wncat,
    const float* __restrict__ lrW1, const float* __restrict__ scrW1, const float* __restrict__ mrW1,
    const float* __restrict__ lrb1, const float* __restrict__ scrb1, const float* __restrict__ mrb1,
    float* __restrict__ Wcat, float* __restrict__ bcat)
{
    const int blk = blockIdx.x, tid = threadIdx.x;
    if (blk < PN_XM_END) {
        int b = blk >> 7, n = blk & 127;
        float4 v = make_float4(0.f, 0.f, 0.f, 0.f);
        if (n < nobj[b]) {
            v = ((const float4*)(nf + (size_t)blk * DNc))[tid];
            v.x = rtf(v.x); v.y = rtf(v.y); v.z = rtf(v.z); v.w = rtf(v.w);
        }
        ((float4*)(Xm + (size_t)blk * DNc))[tid] = v;
    } else if (blk < PN_WN_END) {
        int idx = (blk - PN_XM_END) * 128 + tid;
        int k = idx >> 7, c = idx & 127;
        Wncat[(size_t)k * 256 + c]       = rtf(Wn[idx]);
        Wncat[(size_t)k * 256 + 128 + c] = rtf(Wn2[idx]);
    } else {
        int idx = (blk - PN_WN_END) * 128 + tid;
        int k = idx >> 8, c = idx & 255;
        Wcat[(size_t)k * HID3 + c]             = rtf(lrW1[idx]);
        Wcat[(size_t)k * HID3 + HIDc + c]      = rtf(scrW1[idx]);
        Wcat[(size_t)k * HID3 + 2 * HIDc + c]  = rtf(mrW1[idx]);
        if (blk == PN_WN_END) {
            for (int i = tid; i < HIDc; i += 128) {
                bcat[i]             = lrb1[i];
                bcat[HIDc + i]      = scrb1[i];
                bcat[2 * HIDc + i]  = mrb1[i];
            }
        }
    }
}

// PAIR branch: pairE [0,8192) + We2R [8192,8256)
constexpr int PP_PAIR_END = Bc * Pc;                        // 8192
constexpr int PP_TOTAL    = PP_PAIR_END + (DEc * WEc) / 512; // +64

__global__ void __launch_bounds__(128) k_prep_pair(
    const float* __restrict__ ef, const int* __restrict__ opair, float* __restrict__ pairE,
    const float* __restrict__ We2, float* __restrict__ We2R)
{
    const int blk = blockIdx.x, tid = threadIdx.x;
    if (blk < PP_PAIR_END) {
        int b = blk >> 9, k = blk & 511;
        int p0 = opair[(b * Pc + k) * 2 + 0];
        int p1 = opair[(b * Pc + k) * 2 + 1];
        float2 v = ((const float2*)(ef + (((size_t)b * Nc + p0) * Nc + p1) * DEc))[tid];
        v.x = rtf(v.x); v.y = rtf(v.y);
        ((float2*)(pairE + (size_t)blk * DEc))[tid] = v;
    } else {
        int idx = (blk - PP_PAIR_END) * 128 + tid;
        float4 v = ((const float4*)We2)[idx];
        v.x = rtf(v.x); v.y = rtf(v.y); v.z = rtf(v.z); v.w = rtf(v.w);
        ((float4*)We2R)[idx] = v;
    }
}

// ---------------- sparse adjacency (shared device fn) ----------------
__device__ __forceinline__ void adj_dev(
    const float* __restrict__ Adj, const float* __restrict__ Feat,
    const int* __restrict__ cntArr, float* __restrict__ Out,
    int blk, int ROWLEN, int featStride,
    float* srow, int* sidx, float* sval, int* scount)
{
    const int b   = blk / ROWLEN;
    const int i   = blk % ROWLEN;
    const int tid = threadIdx.x;
    const int cnt = cntArr[b];

    float* outRow = Out + (size_t)blk * 128;
    if (i >= cnt) { outRow[tid] = 0.f; return; }

    const float4* A4 = (const float4*)(Adj + ((size_t)b * ROWLEN + i) * ROWLEN);
    float4* s4 = (float4*)srow;
    for (int j = tid; j < (ROWLEN >> 2); j += 128) s4[j] = A4[j];
    __syncthreads();

    if (tid < 32) {
        int cn = 0;
        for (int base = 0; base < ROWLEN; base += 32) {
            int j = base + tid;
            float v = srow[j];
            bool nz = (v != 0.f) && (j < cnt);
            unsigned msk = __ballot_sync(0xffffffffu, nz);
            int pos = cn + __popc(msk & ((1u << tid) - 1u));
            if (nz) { sidx[pos] = j; sval[pos] = v; }
            cn += __popc(msk);
        }
        if (tid == 0) *scount = cn;
    }
    __syncthreads();

    const int n = *scount;
    const float* Fb = Feat + (size_t)b * ROWLEN * featStride;
    float acc = Fb[(size_t)i * featStride + tid];     // + eye*mask term
    for (int t = 0; t < n; t++)
        acc = fmaf(sval[t], Fb[(size_t)sidx[t] * featStride + tid], acc);
    outRow[tid] = fmaxf(acc, 0.f);
}

__global__ void __launch_bounds__(128) k_adj_node(
    const float* __restrict__ adjN, const float* __restrict__ XWcat,
    const int* __restrict__ nobj, float* __restrict__ h)
{
    __shared__ float srow[Nc];
    __shared__ int   sidx[Nc];
    __shared__ float sval[Nc];
    __shared__ int   scount;
    adj_dev(adjN, XWcat, nobj, h, blockIdx.x, Nc, 256, srow, sidx, sval, &scount);
}

__global__ void __launch_bounds__(128) k_adj_edge(
    const float* __restrict__ adjM, const float* __restrict__ EgWe,
    const int* __restrict__ nedg, float* __restrict__ g)
{
    __shared__ float srow[Mc];
    __shared__ int   sidx[Mc];
    __shared__ float sval[Mc];
    __shared__ int   scount;
    adj_dev(adjM, EgWe, nedg, g, blockIdx.x, Mc, 128, srow, sidx, sval, &scount);
}

// ---------------- CSR scatter-add agg ----------------
__global__ void __launch_bounds__(128) k_agg(
    const float* __restrict__ g, float* __restrict__ agg)
{
    int bn = blockIdx.x;
    int b = bn >> 7, n = bn & 127;
    int off = d_csr_off[b][n];
    int end = d_csr_off[b][n + 1];
    const float* gb = g + (size_t)b * Mc * WEc;
    float acc = 0.f;
    for (int t = off; t < end; t++) {
        int m = d_csr_list[b][t];
        acc += gb[(size_t)m * WEc + threadIdx.x];
    }
    agg[(size_t)bn * WEc + threadIdx.x] = acc;
}

// ---------------- build classifier input (cols 0..384) ----------------
__global__ void __launch_bounds__(128) k_build_ci(
    const int* __restrict__ opair, const int* __restrict__ nobj,
    const float* __restrict__ h, const float* __restrict__ agg,
    const float* __restrict__ XWcat, float* __restrict__ ci)
{
    int bk = blockIdx.x;
    int b = bk >> 9, k = bk & 511;
    int p0 = opair[(b * Pc + k) * 2 + 0];
    int p1 = opair[(b * Pc + k) * 2 + 1];
    int no = nobj[b];
    float nm0 = (p0 < no) ? 1.f : 0.f;
    float nm1 = (p1 < no) ? 1.f : 0.f;
    int c = threadIdx.x;
    const float* hb = h    + (size_t)b * Nc * WNc;
    const float* ab = agg  + (size_t)b * Nc * WEc;
    const float* xb = XWcat + (size_t)b * Nc * 256 + 128;   // Xp = cols [128,256)
    float* co = ci + (size_t)bk * CI;
    co[c]       = rtf(hb[(size_t)p0 * WNc + c] + hb[(size_t)p1 * WNc + c]);
    co[128 + c] = rtf(ab[(size_t)p0 * WEc + c] * nm0 + ab[(size_t)p1 * WEc + c] * nm1);
    co[256 + c] = rtf(fmaxf(xb[(size_t)p0 * 256 + c] + xb[(size_t)p1 * 256 + c], 0.f));
}

// ---------------- fused output layers (lr 9 | cr 6 | mr 17) ----------------
__global__ void __launch_bounds__(128) k_heads_out(
    const float* __restrict__ hid,
    const float* __restrict__ lrW2,  const float* __restrict__ lrb2,
    const float* __restrict__ scrW2, const float* __restrict__ scrb2,
    const float* __restrict__ mrW2,  const float* __restrict__ mrb2,
    float* __restrict__ out)
{
    __shared__ float sh[HID3];
    const int row = blockIdx.x, tid = threadIdx.x;
    const float* hr = hid + (size_t)row * HID3;
    for (int i = tid; i < HID3; i += 128) sh[i] = hr[i];
    __syncthreads();

    const int o    = tid >> 2;
    const int part = tid & 3;
    const float* W2; const float* b2; int off, OUT, oo; float* dst;
    const size_t rows = (size_t)Bc * Pc;
    if (o < 9)       { W2 = lrW2;  b2 = lrb2;  off = 0;   OUT = 9;  oo = o;      dst = out; }
    else if (o < 15) { W2 = scrW2; b2 = scrb2; off = 256; OUT = 6;  oo = o - 9;  dst = out + rows * 9; }
    else             { W2 = mrW2;  b2 = mrb2;  off = 512; OUT = 17; oo = o - 15; dst = out + rows * 15; }

    float acc = 0.f;
    const int k0 = part * 64;
    #pragma unroll 4
    for (int kk = k0; kk < k0 + 64; kk++)
        acc += sh[off + kk] * W2[kk * OUT + oo];
    acc += __shfl_xor_sync(0xffffffffu, acc, 1);
    acc += __shfl_xor_sync(0xffffffffu, acc, 2);
    if (part == 0) dst[(size_t)row * OUT + oo] = acc + b2[oo];
}

// ---------------- launch (3 parallel stream branches, fork/join) ----------------
extern "C" void kernel_launch(void* const* d_in, const int* in_sizes, int n_in,
                              void* d_out, int out_size)
{
    const float* nf    = (const float*)d_in[0];
    const float* ef    = (const float*)d_in[1];
    const float* adj   = (const float*)d_in[2];
    const float* ladj  = (const float*)d_in[3];
    const int*   eidx  = (const int*)d_in[4];
    const int*   opair = (const int*)d_in[5];
    const int*   nobj  = (const int*)d_in[6];
    const int*   nedg  = (const int*)d_in[7];
    const float* Wn    = (const float*)d_in[8];
    const float* We    = (const float*)d_in[9];
    const float* Wn2   = (const float*)d_in[10];
    const float* We2   = (const float*)d_in[11];
    const float* scrW1 = (const float*)d_in[12];
    const float* scrb1 = (const float*)d_in[13];
    const float* scrW2 = (const float*)d_in[14];
    const float* scrb2 = (const float*)d_in[15];
    const float* lrW1  = (const float*)d_in[16];
    const float* lrb1  = (const float*)d_in[17];
    const float* lrW2  = (const float*)d_in[18];
    const float* lrb2  = (const float*)d_in[19];
    const float* mrW1  = (const float*)d_in[20];
    const float* mrb1  = (const float*)d_in[21];
    const float* mrW2  = (const float*)d_in[22];
    const float* mrb2  = (const float*)d_in[23];
    float* out = (float*)d_out;

    float* S = nullptr;
    cudaGetSymbolAddress((void**)&S, d_scratch);
    float* Xm    = S + OFF_XM;
    float* XWcat = S + OFF_XWCAT;
    float* h     = S + OFF_H;
    float* Eg    = S + OFF_EG;
    float* EgWe  = S + OFF_EGWE;
    float* g     = S + OFF_G;
    float* agg   = S + OFF_AGG;
    float* pairE = S + OFF_PAIRE;
    float* ci    = S + OFF_CI;
    float* hid   = S + OFF_HID;
    float* Wncat = S + OFF_WNCAT;
    float* Wcat  = S + OFF_WCAT;
    float* bcat  = S + OFF_BCAT;
    float* WeR   = S + OFF_WER;
    float* We2R  = S + OFF_WE2R;

    cudaStream_t s1, s2;
    cudaStreamCreateWithFlags(&s1, cudaStreamNonBlocking);
    cudaStreamCreateWithFlags(&s2, cudaStreamNonBlocking);
    cudaEvent_t eF, eN, eP;
    cudaEventCreateWithFlags(&eF, cudaEventDisableTiming);
    cudaEventCreateWithFlags(&eN, cudaEventDisableTiming);
    cudaEventCreateWithFlags(&eP, cudaEventDisableTiming);

    // fork
    cudaEventRecord(eF, 0);
    cudaStreamWaitEvent(s1, eF, 0);
    cudaStreamWaitEvent(s2, eF, 0);

    // NODE branch (s1): Xm mask + weight packs -> X@[Wn|Wn2] -> node adjacency
    k_prep_node<<<PN_TOTAL, 128, 0, s1>>>(nf, nobj, Xm, Wn, Wn2, Wncat,
                                          lrW1, scrW1, mrW1, lrb1, scrb1, mrb1, Wcat, bcat);
    k_gemm_node<<<32, 256, 0, s1>>>(Xm, Wncat, XWcat);
    k_adj_node<<<Bc * Nc, 128, 0, s1>>>(adj, XWcat, nobj, h);
    cudaEventRecord(eN, s1);

    // PAIR branch (s2): pairE gather -> relu(pairE@We2) -> ci[:,384:]
    k_prep_pair<<<PP_TOTAL, 128, 0, s2>>>(ef, opair, pairE, We2, We2R);
    k_gemm_pair<<<64, 256, 0, s2>>>(pairE, We2R, ci);
    cudaEventRecord(eP, s2);

    // EDGE branch (origin): Eg gather + CSR -> Eg@We -> line adjacency -> agg
    k_prep_edge<<<PE_TOTAL, 128>>>(ef, eidx, nedg, Eg, We, WeR);
    k_gemm_edge<<<128, 256>>>(Eg, WeR, EgWe);
    k_adj_edge<<<Bc * Mc, 128>>>(ladj, EgWe, nedg, g);
    k_agg<<<Bc * Nc, 128>>>(g, agg);

    // join
    cudaStreamWaitEvent(0, eN, 0);
    cudaStreamWaitEvent(0, eP, 0);

    // tail: ci cols 0..384, heads GEMM, output layers
    k_build_ci<<<Bc * Pc, 128>>>(opair, nobj, h, agg, XWcat, ci);
    k_gemm_heads<<<(Bc * Pc / 128) * 6, 256>>>(ci, Wcat, bcat, hid);
    k_heads_out<<<Bc * Pc, 128>>>(hid, lrW2, lrb2, scrW2, scrb2, mrW2, mrb2, out);

    cudaEventDestroy(eF);
    cudaEventDestroy(eN);
    cudaEventDestroy(eP);
    cudaStreamDestroy(s1);
    cudaStreamDestroy(s2);
}